// round 1
// baseline (speedup 1.0000x reference)
#include <cuda_runtime.h>
#include <math.h>

#define B_ 32
#define T_ 64
#define E_ 256
#define H_ 256
#define P_ 63
#define PB_ 2016
#define NPACK_ 64512

// ------------------------- scratch (device globals; no allocs) -------------
__device__ float g_emb[T_*B_*E_];              // (t*B+b, E)
__device__ float g_gxa[T_*B_*3*H_];            // input gates GRU a
__device__ float g_gxb[T_*B_*3*H_];            // input gates GRU b
__device__ float g_ha[2][PB_*H_];              // ping-pong hidden, GRU a
__device__ float g_hb[2][PB_*H_];              // ping-pong hidden, GRU b
__device__ float g_fa[(size_t)NPACK_*H_];      // packed 0.5*h states, GRU a
__device__ float g_fb[(size_t)NPACK_*H_];      // packed 0.5*h states, GRU b
__device__ float g_beta[(size_t)NPACK_*E_];    // tanh(fb @ beta_w^T + b)
__device__ float g_ebeta[(size_t)NPACK_*E_];   // beta @ M
__device__ float g_pre[P_*T_*B_];
__device__ float g_alpha[P_*T_*B_];
__device__ float g_Mt[E_*E_];                  // Mt[i][e] = out_w[e]*emb_w[e,i]

// ------------------------- small kernels -----------------------------------
__global__ void zero_h_kernel() {
    int i = blockIdx.x*256 + threadIdx.x;
    if (i < PB_*H_) { g_ha[0][i] = 0.f; g_hb[0][i] = 0.f; }
}

__global__ void prep_mt_kernel(const float* __restrict__ emb_w,
                               const float* __restrict__ out_w) {
    int i = blockIdx.x;    // output-contrib index (I)
    int e = threadIdx.x;   // E index
    g_Mt[i*E_ + e] = out_w[e] * emb_w[e*E_ + i];
}

// ------------------------- generic NT GEMM (K=256) --------------------------
// C[m,n] = act( sum_k A[m,k]*Bt[n,k] + bias[n] ).  BM=BN=64, BK=16, 256 thr.
// xmode=1: A row m=(t*B+b) read from x[b,t,:] (x is (B,T,I)).
__global__ void gemm_nt(const float* __restrict__ A, const float* __restrict__ Bt,
                        const float* __restrict__ bias, float* __restrict__ C,
                        int M, int N, int act, int xmode) {
    __shared__ float As[16][64];
    __shared__ float Bs[16][64];
    int tid = threadIdx.x;
    int m0 = blockIdx.x*64, n0 = blockIdx.y*64;
    int tx = tid & 15, ty = tid >> 4;
    int lr = tid >> 2, lk = (tid & 3)*4;
    float acc[4][4] = {};
    int am = m0 + lr;
    const float* arow;
    if (xmode) {
        int t = am >> 5, b = am & 31;
        arow = A + ((size_t)b*T_ + t)*E_;
    } else {
        arow = A + (size_t)am*256;
    }
    const float* brow = Bt + (size_t)(n0 + lr)*256;
    for (int k0 = 0; k0 < 256; k0 += 16) {
        float4 av = *(const float4*)(arow + k0 + lk);
        float4 bv = *(const float4*)(brow + k0 + lk);
        As[lk+0][lr]=av.x; As[lk+1][lr]=av.y; As[lk+2][lr]=av.z; As[lk+3][lr]=av.w;
        Bs[lk+0][lr]=bv.x; Bs[lk+1][lr]=bv.y; Bs[lk+2][lr]=bv.z; Bs[lk+3][lr]=bv.w;
        __syncthreads();
#pragma unroll
        for (int kk = 0; kk < 16; kk++) {
            float4 a4 = *(const float4*)&As[kk][ty*4];
            float4 b4 = *(const float4*)&Bs[kk][tx*4];
            float ar[4] = {a4.x,a4.y,a4.z,a4.w};
            float br[4] = {b4.x,b4.y,b4.z,b4.w};
#pragma unroll
            for (int i=0;i<4;i++)
#pragma unroll
                for (int j=0;j<4;j++) acc[i][j] = fmaf(ar[i], br[j], acc[i][j]);
        }
        __syncthreads();
    }
#pragma unroll
    for (int i=0;i<4;i++) {
        int m = m0 + ty*4 + i;
        if (m >= M) continue;
#pragma unroll
        for (int j=0;j<4;j++) {
            int n = n0 + tx*4 + j;
            float v = acc[i][j];
            if (bias) v += bias[n];
            if (act == 1) v = tanhf(v);
            C[(size_t)m*N + n] = v;
        }
    }
}

// ------------------------- fused GRU step -----------------------------------
// One step k for both GRUs (blockIdx.z). Computes the recurrent GEMM
// (rows [k*32, PB) x 3 gates x 64 cols per col-block), applies gate math,
// writes new h (ping-pong) and the packed 0.5*h state.
__global__ void gru_step_kernel(int k, int offk, int par,
        const float* __restrict__ whh_a, const float* __restrict__ whh_b,
        const float* __restrict__ bhh_a, const float* __restrict__ bhh_b) {
    int gru = blockIdx.z;
    const float* H_in  = gru ? g_hb[par]   : g_ha[par];
    float*       H_out = gru ? g_hb[par^1] : g_ha[par^1];
    const float* W     = gru ? whh_b : whh_a;
    const float* bhh   = gru ? bhh_b : bhh_a;
    const float* gx    = gru ? g_gxb : g_gxa;
    float*       pk    = gru ? g_fb  : g_fa;

    __shared__ float As[16][64];
    __shared__ float Bs[3][16][64];
    int tid = threadIdx.x;
    int rowbase = k*32 + blockIdx.x*64;
    int cbase = blockIdx.y*64;
    int tx = tid & 15, ty = tid >> 4;
    int lr = tid >> 2, lk = (tid & 3)*4;
    float acc[3][4][4] = {};
    int arow_i = rowbase + lr; if (arow_i > PB_-1) arow_i = PB_-1;
    const float* arow = H_in + (size_t)arow_i*H_;
    for (int k0 = 0; k0 < 256; k0 += 16) {
        float4 av = *(const float4*)(arow + k0 + lk);
        As[lk+0][lr]=av.x; As[lk+1][lr]=av.y; As[lk+2][lr]=av.z; As[lk+3][lr]=av.w;
#pragma unroll
        for (int g=0; g<3; g++) {
            float4 bv = *(const float4*)(W + (size_t)(g*H_ + cbase + lr)*H_ + k0 + lk);
            Bs[g][lk+0][lr]=bv.x; Bs[g][lk+1][lr]=bv.y; Bs[g][lk+2][lr]=bv.z; Bs[g][lk+3][lr]=bv.w;
        }
        __syncthreads();
#pragma unroll
        for (int kk=0; kk<16; kk++) {
            float4 a4 = *(const float4*)&As[kk][ty*4];
            float ar[4] = {a4.x,a4.y,a4.z,a4.w};
#pragma unroll
            for (int g=0; g<3; g++) {
                float4 b4 = *(const float4*)&Bs[g][kk][tx*4];
                float br[4] = {b4.x,b4.y,b4.z,b4.w};
#pragma unroll
                for (int i=0;i<4;i++)
#pragma unroll
                    for (int j=0;j<4;j++) acc[g][i][j] = fmaf(ar[i], br[j], acc[g][i][j]);
            }
        }
        __syncthreads();
    }
#pragma unroll
    for (int i=0;i<4;i++) {
        int row = rowbase + ty*4 + i;
        if (row >= PB_) continue;
        const float* gxr = gx + (size_t)(row - k*32)*(3*H_);
        size_t prow = (size_t)(offk + row - k*32);
#pragma unroll
        for (int j=0;j<4;j++) {
            int jg = cbase + tx*4 + j;
            float gr = acc[0][i][j] + bhh[jg]      + gxr[jg];
            float gz = acc[1][i][j] + bhh[H_+jg]   + gxr[H_+jg];
            float gn = acc[2][i][j] + bhh[2*H_+jg];
            float r = 1.f/(1.f + expf(-gr));
            float z = 1.f/(1.f + expf(-gz));
            float n = tanhf(gxr[2*H_+jg] + r*gn);
            float h = H_in[(size_t)row*H_ + jg];
            float hn = (1.f - z)*n + z*h;
            H_out[(size_t)row*H_ + jg] = hn;
            pk[prow*H_ + jg] = 0.5f*hn;
        }
    }
}

// ------------------------- pre / alpha / reduce -----------------------------
__global__ void pre_kernel(const float* __restrict__ alpha_w,
                           const float* __restrict__ alpha_b) {
    int gw = (blockIdx.x*blockDim.x + threadIdx.x) >> 5;
    int lane = threadIdx.x & 31;
    if (gw >= NPACK_) return;
    int k = 0, off = 0;
    while (k < 62 && off + (63-k)*32 <= gw) { off += (63-k)*32; k++; }
    int l = gw - off;
    int t = l >> 5, b = l & 31;
    int p = k + t;
    const float* fa = g_fa + (size_t)gw*H_;
    float s = 0.f;
    for (int e = lane; e < H_; e += 32) s += fa[e]*alpha_w[e];
#pragma unroll
    for (int o=16;o;o>>=1) s += __shfl_xor_sync(0xffffffffu, s, o);
    if (lane == 0) g_pre[(p*T_ + t)*B_ + b] = s + alpha_b[0];
}

__global__ void alpha_kernel() {
    int gw = (blockIdx.x*blockDim.x + threadIdx.x) >> 5;
    int lane = threadIdx.x & 31;
    if (gw >= PB_) return;
    int p = gw >> 5, b = gw & 31;
    float v0 = (lane      <= p) ? g_pre[(p*T_+lane   )*B_+b] : -1e30f;
    float v1 = (lane + 32 <= p) ? g_pre[(p*T_+lane+32)*B_+b] : -1e30f;
    float m = fmaxf(v0, v1);
#pragma unroll
    for (int o=16;o;o>>=1) m = fmaxf(m, __shfl_xor_sync(0xffffffffu, m, o));
    float e0 = (lane      <= p) ? expf(v0-m) : 0.f;
    float e1 = (lane + 32 <= p) ? expf(v1-m) : 0.f;
    float s = e0 + e1;
#pragma unroll
    for (int o=16;o;o>>=1) s += __shfl_xor_sync(0xffffffffu, s, o);
    float inv = 1.f/s;
    g_alpha[(p*T_+lane   )*B_+b] = e0*inv;
    g_alpha[(p*T_+lane+32)*B_+b] = e1*inv;
}

__global__ void reduce_kernel(const float* __restrict__ x,
                              const float* __restrict__ out_w,
                              const float* __restrict__ out_b,
                              float* __restrict__ out) {
    int pb = blockIdx.x;
    int p = pb >> 5, b = pb & 31;
    int e = threadIdx.x;
    float cc = 0.f, gg = 0.f;
    for (int t = 0; t <= p; t++) {
        float a = g_alpha[(p*T_+t)*B_+b];
        int kk = p - t;
        int offk = 32*(63*kk - (kk*(kk-1))/2);
        size_t prow = (size_t)offk + t*32 + b;
        cc += a * g_beta [prow*E_ + e] * g_emb[((size_t)(t*B_+b))*E_ + e];
        gg += a * g_ebeta[prow*E_ + e] * x[((size_t)b*T_ + t)*E_ + e];
    }
    out[B_*P_ + ((size_t)(b*P_+p))*E_ + e] = gg / (float)(p+1);
    __shared__ float red[256];
    red[e] = cc * out_w[e];
    __syncthreads();
    for (int s2=128; s2; s2>>=1) { if (e < s2) red[e] += red[e+s2]; __syncthreads(); }
    if (e == 0) out[b*P_ + p] = red[0] + out_b[0];
}

// ------------------------- launch ------------------------------------------
extern "C" void kernel_launch(void* const* d_in, const int* in_sizes, int n_in,
                              void* d_out, int out_size) {
    (void)in_sizes; (void)n_in; (void)out_size;
    const float* x       = (const float*)d_in[0];
    const float* emb_w   = (const float*)d_in[1];
    const float* emb_b   = (const float*)d_in[2];
    const float* a_wih   = (const float*)d_in[3];
    const float* a_whh   = (const float*)d_in[4];
    const float* a_bih   = (const float*)d_in[5];
    const float* a_bhh   = (const float*)d_in[6];
    const float* b_wih   = (const float*)d_in[7];
    const float* b_whh   = (const float*)d_in[8];
    const float* b_bih   = (const float*)d_in[9];
    const float* b_bhh   = (const float*)d_in[10];
    const float* alpha_w = (const float*)d_in[11];
    const float* alpha_b = (const float*)d_in[12];
    const float* beta_w  = (const float*)d_in[13];
    const float* beta_b  = (const float*)d_in[14];
    const float* out_w   = (const float*)d_in[15];
    const float* out_b   = (const float*)d_in[16];
    float* out = (float*)d_out;

    float *p_emb=0, *p_gxa=0, *p_gxb=0, *p_fb=0, *p_beta=0, *p_ebeta=0, *p_Mt=0;
    cudaGetSymbolAddress((void**)&p_emb,   g_emb);
    cudaGetSymbolAddress((void**)&p_gxa,   g_gxa);
    cudaGetSymbolAddress((void**)&p_gxb,   g_gxb);
    cudaGetSymbolAddress((void**)&p_fb,    g_fb);
    cudaGetSymbolAddress((void**)&p_beta,  g_beta);
    cudaGetSymbolAddress((void**)&p_ebeta, g_ebeta);
    cudaGetSymbolAddress((void**)&p_Mt,    g_Mt);

    zero_h_kernel<<<(PB_*H_ + 255)/256, 256>>>();
    prep_mt_kernel<<<E_, E_>>>(emb_w, out_w);
    // emb = xt @ emb_w^T + emb_b      (2048 x 256, K=256), A read from x (B,T,I)
    gemm_nt<<<dim3((T_*B_)/64, E_/64), 256>>>(x, emb_w, emb_b, p_emb, T_*B_, E_, 0, 1);
    // input-gate precompute for both GRUs (2048 x 768)
    gemm_nt<<<dim3((T_*B_)/64, (3*H_)/64), 256>>>(p_emb, a_wih, a_bih, p_gxa, T_*B_, 3*H_, 0, 0);
    gemm_nt<<<dim3((T_*B_)/64, (3*H_)/64), 256>>>(p_emb, b_wih, b_bih, p_gxb, T_*B_, 3*H_, 0, 0);

    // 63 recurrence steps, shrinking active rows, both GRUs per launch
    int offk = 0, par = 0;
    for (int k = 0; k < 63; k++) {
        int active = (63-k)*32;
        int nb = (active + 63)/64;
        gru_step_kernel<<<dim3(nb, 4, 2), 256>>>(k, offk, par, a_whh, b_whh, a_bhh, b_bhh);
        offk += active;
        par ^= 1;
    }

    pre_kernel<<<(NPACK_*32 + 255)/256, 256>>>(alpha_w, alpha_b);
    alpha_kernel<<<(PB_*32 + 255)/256, 256>>>();
    // beta = tanh(fb @ beta_w^T + beta_b)   (64512 x 256)
    gemm_nt<<<dim3(NPACK_/64, E_/64), 256>>>(p_fb, beta_w, beta_b, p_beta, NPACK_, E_, 1, 0);
    // ebeta = beta @ M                      (64512 x 256)
    gemm_nt<<<dim3(NPACK_/64, E_/64), 256>>>(p_beta, p_Mt, 0, p_ebeta, NPACK_, E_, 0, 0);
    reduce_kernel<<<PB_, 256>>>(x, out_w, out_b, out);
}

// round 2
// speedup vs baseline: 1.1721x; 1.1721x over previous
#include <cuda_runtime.h>
#include <math.h>

#define B_ 32
#define T_ 64
#define E_ 256
#define H_ 256
#define P_ 63
#define PB_ 2016
#define NPACK_ 64512

// ------------------------- scratch (device globals; no allocs) -------------
__device__ float g_emb[T_*B_*E_];              // (t*B+b, E)
__device__ float g_gxa[T_*B_*3*H_];            // input gates GRU a
__device__ float g_gxb[T_*B_*3*H_];            // input gates GRU b
__device__ float g_ha[2][PB_*H_];              // ping-pong hidden, GRU a
__device__ float g_hb[2][PB_*H_];              // ping-pong hidden, GRU b
__device__ float g_fa[(size_t)NPACK_*H_];      // packed 0.5*h states, GRU a
__device__ float g_fb[(size_t)NPACK_*H_];      // packed 0.5*h states, GRU b
__device__ float g_beta[(size_t)NPACK_*E_];    // tanh(fb @ beta_w^T + b)
__device__ float g_ebeta[(size_t)NPACK_*E_];   // beta @ M
__device__ float g_pre[P_*T_*B_];
__device__ float g_alpha[P_*T_*B_];
__device__ float g_Mt[E_*E_];                  // Mt[i][e] = out_w[e]*emb_w[e,i]

// ------------------------- small kernels -----------------------------------
__global__ void zero_h_kernel() {
    int i = blockIdx.x*256 + threadIdx.x;
    if (i < PB_*H_) { g_ha[0][i] = 0.f; g_hb[0][i] = 0.f; }
}

__global__ void prep_mt_kernel(const float* __restrict__ emb_w,
                               const float* __restrict__ out_w) {
    int i = blockIdx.x;    // output-contrib index (I)
    int e = threadIdx.x;   // E index
    g_Mt[i*E_ + e] = out_w[e] * emb_w[e*E_ + i];
}

__device__ __forceinline__ const float* arow_ptr(const float* A, int m, int xmode) {
    if (xmode) { int t = m >> 5, b = m & 31; return A + ((size_t)b*T_ + t)*E_; }
    return A + (size_t)m*E_;
}

// ------------------------- 128x128 NT SGEMM (K=256) -------------------------
// C[m,n] = act( sum_k A[m,k]*Bt[n,k] + bias[n] ). Double-buffered, 8x8 micro.
__global__ void __launch_bounds__(256, 2)
sgemm128(const float* __restrict__ A, const float* __restrict__ Bt,
         const float* __restrict__ bias, float* __restrict__ C,
         int N, int act, int xmode) {
    __shared__ float As[2][8][128];
    __shared__ float Bs[2][8][128];
    const int tid = threadIdx.x;
    const int m0 = blockIdx.x * 128, n0 = blockIdx.y * 128;
    const int tx = tid & 15, ty = tid >> 4;
    const int lr = tid >> 1;            // 0..127
    const int ks = (tid & 1) * 4;       // 0 or 4
    const float* pA = arow_ptr(A, m0 + lr, xmode) + ks;
    const float* pB = Bt + (size_t)(n0 + lr) * 256 + ks;

    float acc[2][2][4][4] = {};
    float4 va = *(const float4*)pA;
    float4 vb = *(const float4*)pB;
    {
        const float* f = (const float*)&va;
#pragma unroll
        for (int j = 0; j < 4; j++) As[0][ks+j][lr] = f[j];
        f = (const float*)&vb;
#pragma unroll
        for (int j = 0; j < 4; j++) Bs[0][ks+j][lr] = f[j];
    }
    __syncthreads();
    int buf = 0;
#pragma unroll 1
    for (int c = 0; c < 32; c++) {
        if (c < 31) {
            int off = (c+1)*8;
            va = *(const float4*)(pA + off);
            vb = *(const float4*)(pB + off);
        }
#pragma unroll
        for (int kk = 0; kk < 8; kk++) {
            float4 a0 = *(const float4*)&As[buf][kk][ty*4];
            float4 a1 = *(const float4*)&As[buf][kk][ty*4 + 64];
            float4 b0 = *(const float4*)&Bs[buf][kk][tx*4];
            float4 b1 = *(const float4*)&Bs[buf][kk][tx*4 + 64];
            float aa[2][4] = {{a0.x,a0.y,a0.z,a0.w},{a1.x,a1.y,a1.z,a1.w}};
            float bb[2][4] = {{b0.x,b0.y,b0.z,b0.w},{b1.x,b1.y,b1.z,b1.w}};
#pragma unroll
            for (int rh = 0; rh < 2; rh++)
#pragma unroll
            for (int i = 0; i < 4; i++)
#pragma unroll
            for (int ch = 0; ch < 2; ch++)
#pragma unroll
            for (int j = 0; j < 4; j++)
                acc[rh][ch][i][j] = fmaf(aa[rh][i], bb[ch][j], acc[rh][ch][i][j]);
        }
        if (c < 31) {
            int nb = buf ^ 1;
            const float* f = (const float*)&va;
#pragma unroll
            for (int j = 0; j < 4; j++) As[nb][ks+j][lr] = f[j];
            f = (const float*)&vb;
#pragma unroll
            for (int j = 0; j < 4; j++) Bs[nb][ks+j][lr] = f[j];
            __syncthreads();
            buf = nb;
        }
    }
#pragma unroll
    for (int rh = 0; rh < 2; rh++)
#pragma unroll
    for (int i = 0; i < 4; i++) {
        int m = m0 + rh*64 + ty*4 + i;
#pragma unroll
        for (int ch = 0; ch < 2; ch++) {
            int n = n0 + ch*64 + tx*4;
            float4 v;
            v.x = acc[rh][ch][i][0]; v.y = acc[rh][ch][i][1];
            v.z = acc[rh][ch][i][2]; v.w = acc[rh][ch][i][3];
            if (bias) {
                float4 bz = *(const float4*)&bias[n];
                v.x += bz.x; v.y += bz.y; v.z += bz.z; v.w += bz.w;
            }
            if (act == 1) {
                v.x = tanhf(v.x); v.y = tanhf(v.y);
                v.z = tanhf(v.z); v.w = tanhf(v.w);
            }
            *(float4*)&C[(size_t)m*N + n] = v;
        }
    }
}

// ------------------------- fused GRU step (double-buffered) -----------------
// One step k for both GRUs (blockIdx.z). 64 rows x 64 cols x 3 gates / block.
__global__ void __launch_bounds__(256, 2)
gru_step_kernel(int k, int offk, int par,
        const float* __restrict__ whh_a, const float* __restrict__ whh_b,
        const float* __restrict__ bhh_a, const float* __restrict__ bhh_b) {
    int gru = blockIdx.z;
    const float* H_in  = gru ? g_hb[par]   : g_ha[par];
    float*       H_out = gru ? g_hb[par^1] : g_ha[par^1];
    const float* W     = gru ? whh_b : whh_a;
    const float* bhh   = gru ? bhh_b : bhh_a;
    const float* gx    = gru ? g_gxb : g_gxa;
    float*       pk    = gru ? g_fb  : g_fa;

    __shared__ float As[2][16][64];
    __shared__ float Bs[2][3][16][64];
    const int tid = threadIdx.x;
    const int rowbase = k*32 + blockIdx.x*64;
    const int cbase = blockIdx.y*64;
    const int tx = tid & 15, ty = tid >> 4;
    const int lr = tid >> 2;            // 0..63
    const int ks = (tid & 3) * 4;       // 0,4,8,12
    int arow_i = rowbase + lr; if (arow_i > PB_-1) arow_i = PB_-1;
    const float* pA  = H_in + (size_t)arow_i*H_ + ks;
    const float* pB0 = W + (size_t)(         cbase + lr)*H_ + ks;
    const float* pB1 = W + (size_t)(H_     + cbase + lr)*H_ + ks;
    const float* pB2 = W + (size_t)(2*H_   + cbase + lr)*H_ + ks;

    float acc[3][4][4] = {};
    float4 va = *(const float4*)pA;
    float4 v0 = *(const float4*)pB0;
    float4 v1 = *(const float4*)pB1;
    float4 v2 = *(const float4*)pB2;
    {
        const float* f = (const float*)&va;
#pragma unroll
        for (int j = 0; j < 4; j++) As[0][ks+j][lr] = f[j];
        f = (const float*)&v0;
#pragma unroll
        for (int j = 0; j < 4; j++) Bs[0][0][ks+j][lr] = f[j];
        f = (const float*)&v1;
#pragma unroll
        for (int j = 0; j < 4; j++) Bs[0][1][ks+j][lr] = f[j];
        f = (const float*)&v2;
#pragma unroll
        for (int j = 0; j < 4; j++) Bs[0][2][ks+j][lr] = f[j];
    }
    __syncthreads();
    int buf = 0;
#pragma unroll 1
    for (int c = 0; c < 16; c++) {
        if (c < 15) {
            int off = (c+1)*16;
            va = *(const float4*)(pA  + off);
            v0 = *(const float4*)(pB0 + off);
            v1 = *(const float4*)(pB1 + off);
            v2 = *(const float4*)(pB2 + off);
        }
#pragma unroll
        for (int kk = 0; kk < 16; kk++) {
            float4 a4 = *(const float4*)&As[buf][kk][ty*4];
            float ar[4] = {a4.x,a4.y,a4.z,a4.w};
#pragma unroll
            for (int g = 0; g < 3; g++) {
                float4 b4 = *(const float4*)&Bs[buf][g][kk][tx*4];
                float br[4] = {b4.x,b4.y,b4.z,b4.w};
#pragma unroll
                for (int i = 0; i < 4; i++)
#pragma unroll
                for (int j = 0; j < 4; j++)
                    acc[g][i][j] = fmaf(ar[i], br[j], acc[g][i][j]);
            }
        }
        if (c < 15) {
            int nb = buf ^ 1;
            const float* f = (const float*)&va;
#pragma unroll
            for (int j = 0; j < 4; j++) As[nb][ks+j][lr] = f[j];
            f = (const float*)&v0;
#pragma unroll
            for (int j = 0; j < 4; j++) Bs[nb][0][ks+j][lr] = f[j];
            f = (const float*)&v1;
#pragma unroll
            for (int j = 0; j < 4; j++) Bs[nb][1][ks+j][lr] = f[j];
            f = (const float*)&v2;
#pragma unroll
            for (int j = 0; j < 4; j++) Bs[nb][2][ks+j][lr] = f[j];
            __syncthreads();
            buf = nb;
        }
    }
#pragma unroll
    for (int i = 0; i < 4; i++) {
        int row = rowbase + ty*4 + i;
        if (row >= PB_) continue;
        const float* gxr = gx + (size_t)(row - k*32)*(3*H_);
        size_t prow = (size_t)(offk + row - k*32);
#pragma unroll
        for (int j = 0; j < 4; j++) {
            int jg = cbase + tx*4 + j;
            float gr = acc[0][i][j] + bhh[jg]      + gxr[jg];
            float gz = acc[1][i][j] + bhh[H_+jg]   + gxr[H_+jg];
            float gn = acc[2][i][j] + bhh[2*H_+jg];
            float r = 1.f/(1.f + expf(-gr));
            float z = 1.f/(1.f + expf(-gz));
            float n = tanhf(gxr[2*H_+jg] + r*gn);
            float h = H_in[(size_t)row*H_ + jg];
            float hn = (1.f - z)*n + z*h;
            H_out[(size_t)row*H_ + jg] = hn;
            pk[prow*H_ + jg] = 0.5f*hn;
        }
    }
}

// ------------------------- pre / alpha / reduce -----------------------------
__global__ void pre_kernel(const float* __restrict__ alpha_w,
                           const float* __restrict__ alpha_b) {
    int gw = (blockIdx.x*blockDim.x + threadIdx.x) >> 5;
    int lane = threadIdx.x & 31;
    if (gw >= NPACK_) return;
    int k = 0, off = 0;
    while (k < 62 && off + (63-k)*32 <= gw) { off += (63-k)*32; k++; }
    int l = gw - off;
    int t = l >> 5, b = l & 31;
    int p = k + t;
    const float* fa = g_fa + (size_t)gw*H_;
    float s = 0.f;
    for (int e = lane; e < H_; e += 32) s += fa[e]*alpha_w[e];
#pragma unroll
    for (int o=16;o;o>>=1) s += __shfl_xor_sync(0xffffffffu, s, o);
    if (lane == 0) g_pre[(p*T_ + t)*B_ + b] = s + alpha_b[0];
}

__global__ void alpha_kernel() {
    int gw = (blockIdx.x*blockDim.x + threadIdx.x) >> 5;
    int lane = threadIdx.x & 31;
    if (gw >= PB_) return;
    int p = gw >> 5, b = gw & 31;
    float v0 = (lane      <= p) ? g_pre[(p*T_+lane   )*B_+b] : -1e30f;
    float v1 = (lane + 32 <= p) ? g_pre[(p*T_+lane+32)*B_+b] : -1e30f;
    float m = fmaxf(v0, v1);
#pragma unroll
    for (int o=16;o;o>>=1) m = fmaxf(m, __shfl_xor_sync(0xffffffffu, m, o));
    float e0 = (lane      <= p) ? expf(v0-m) : 0.f;
    float e1 = (lane + 32 <= p) ? expf(v1-m) : 0.f;
    float s = e0 + e1;
#pragma unroll
    for (int o=16;o;o>>=1) s += __shfl_xor_sync(0xffffffffu, s, o);
    float inv = 1.f/s;
    g_alpha[(p*T_+lane   )*B_+b] = e0*inv;
    g_alpha[(p*T_+lane+32)*B_+b] = e1*inv;
}

__global__ void reduce_kernel(const float* __restrict__ x,
                              const float* __restrict__ out_w,
                              const float* __restrict__ out_b,
                              float* __restrict__ out) {
    int pb = blockIdx.x;
    int p = pb >> 5, b = pb & 31;
    int e = threadIdx.x;
    float cc = 0.f, gg = 0.f;
    for (int t = 0; t <= p; t++) {
        float a = g_alpha[(p*T_+t)*B_+b];
        int kk = p - t;
        int offk = 32*(63*kk - (kk*(kk-1))/2);
        size_t prow = (size_t)offk + t*32 + b;
        cc += a * g_beta [prow*E_ + e] * g_emb[((size_t)(t*B_+b))*E_ + e];
        gg += a * g_ebeta[prow*E_ + e] * x[((size_t)b*T_ + t)*E_ + e];
    }
    out[B_*P_ + ((size_t)(b*P_+p))*E_ + e] = gg / (float)(p+1);
    __shared__ float red[256];
    red[e] = cc * out_w[e];
    __syncthreads();
    for (int s2=128; s2; s2>>=1) { if (e < s2) red[e] += red[e+s2]; __syncthreads(); }
    if (e == 0) out[b*P_ + p] = red[0] + out_b[0];
}

// ------------------------- launch ------------------------------------------
extern "C" void kernel_launch(void* const* d_in, const int* in_sizes, int n_in,
                              void* d_out, int out_size) {
    (void)in_sizes; (void)n_in; (void)out_size;
    const float* x       = (const float*)d_in[0];
    const float* emb_w   = (const float*)d_in[1];
    const float* emb_b   = (const float*)d_in[2];
    const float* a_wih   = (const float*)d_in[3];
    const float* a_whh   = (const float*)d_in[4];
    const float* a_bih   = (const float*)d_in[5];
    const float* a_bhh   = (const float*)d_in[6];
    const float* b_wih   = (const float*)d_in[7];
    const float* b_whh   = (const float*)d_in[8];
    const float* b_bih   = (const float*)d_in[9];
    const float* b_bhh   = (const float*)d_in[10];
    const float* alpha_w = (const float*)d_in[11];
    const float* alpha_b = (const float*)d_in[12];
    const float* beta_w  = (const float*)d_in[13];
    const float* beta_b  = (const float*)d_in[14];
    const float* out_w   = (const float*)d_in[15];
    const float* out_b   = (const float*)d_in[16];
    float* out = (float*)d_out;

    float *p_emb=0, *p_gxa=0, *p_gxb=0, *p_fb=0, *p_beta=0, *p_ebeta=0, *p_Mt=0;
    cudaGetSymbolAddress((void**)&p_emb,   g_emb);
    cudaGetSymbolAddress((void**)&p_gxa,   g_gxa);
    cudaGetSymbolAddress((void**)&p_gxb,   g_gxb);
    cudaGetSymbolAddress((void**)&p_fb,    g_fb);
    cudaGetSymbolAddress((void**)&p_beta,  g_beta);
    cudaGetSymbolAddress((void**)&p_ebeta, g_ebeta);
    cudaGetSymbolAddress((void**)&p_Mt,    g_Mt);

    zero_h_kernel<<<(PB_*H_ + 255)/256, 256>>>();
    prep_mt_kernel<<<E_, E_>>>(emb_w, out_w);
    // emb = xt @ emb_w^T + emb_b      (2048 x 256, K=256), A read from x (B,T,I)
    sgemm128<<<dim3((T_*B_)/128, E_/128), 256>>>(x, emb_w, emb_b, p_emb, E_, 0, 1);
    // input-gate precompute for both GRUs (2048 x 768)
    sgemm128<<<dim3((T_*B_)/128, (3*H_)/128), 256>>>(p_emb, a_wih, a_bih, p_gxa, 3*H_, 0, 0);
    sgemm128<<<dim3((T_*B_)/128, (3*H_)/128), 256>>>(p_emb, b_wih, b_bih, p_gxb, 3*H_, 0, 0);

    // 63 recurrence steps, shrinking active rows, both GRUs per launch
    int offk = 0, par = 0;
    for (int k = 0; k < 63; k++) {
        int active = (63-k)*32;
        int nb = (active + 63)/64;
        gru_step_kernel<<<dim3(nb, 4, 2), 256>>>(k, offk, par, a_whh, b_whh, a_bhh, b_bhh);
        offk += active;
        par ^= 1;
    }

    pre_kernel<<<(NPACK_*32 + 255)/256, 256>>>(alpha_w, alpha_b);
    alpha_kernel<<<(PB_*32 + 255)/256, 256>>>();
    // beta = tanh(fb @ beta_w^T + beta_b)   (64512 x 256)
    sgemm128<<<dim3(NPACK_/128, E_/128), 256>>>(p_fb, beta_w, beta_b, p_beta, E_, 1, 0);
    // ebeta = beta @ M                      (64512 x 256)
    sgemm128<<<dim3(NPACK_/128, E_/128), 256>>>(p_beta, p_Mt, 0, p_ebeta, E_, 0, 0);
    reduce_kernel<<<PB_, 256>>>(x, out_w, out_b, out);
}

// round 4
// speedup vs baseline: 1.2080x; 1.0307x over previous
#include <cuda_runtime.h>
#include <cuda_bf16.h>
#include <math.h>
#include <stdint.h>

#define B_ 32
#define T_ 64
#define E_ 256
#define H_ 256
#define P_ 63
#define PB_ 2016
#define NPACK_ 64512
#define PITCH 24   // bf16 elements per smem row (16 data + 8 pad)

// ------------------------- scratch (device globals) -------------------------
__device__ float g_emb[T_*B_*E_];
__device__ float g_gxa[T_*B_*3*H_];
__device__ float g_gxb[T_*B_*3*H_];
__device__ __nv_bfloat16 g_hhi[2][2][PB_*H_];   // [gru][parity]
__device__ __nv_bfloat16 g_hlo[2][2][PB_*H_];
__device__ __nv_bfloat16 g_whi[2][3*H_*H_];     // recurrent weights, hi plane
__device__ __nv_bfloat16 g_wlo[2][3*H_*H_];
__device__ __nv_bfloat16 g_bwhi[E_*H_];         // beta_w planes  [n][k]
__device__ __nv_bfloat16 g_bwlo[E_*H_];
__device__ __nv_bfloat16 g_mthi[E_*E_];         // Mt planes [i][e]
__device__ __nv_bfloat16 g_mtlo[E_*E_];
__device__ float g_fa[(size_t)NPACK_*H_];
__device__ __nv_bfloat16 g_fbhi[(size_t)NPACK_*H_];
__device__ __nv_bfloat16 g_fblo[(size_t)NPACK_*H_];
__device__ float g_beta[(size_t)NPACK_*E_];
__device__ __nv_bfloat16 g_betahi[(size_t)NPACK_*E_];
__device__ __nv_bfloat16 g_betalo[(size_t)NPACK_*E_];
__device__ float g_ebeta[(size_t)NPACK_*E_];
__device__ float g_pre[P_*T_*B_];
__device__ float g_alpha[P_*T_*B_];

// ------------------------- mma / ldmatrix helpers ---------------------------
__device__ __forceinline__ uint32_t smem_u32(const void* p) {
    uint32_t a;
    asm("{ .reg .u64 t; cvta.to.shared.u64 t, %1; cvt.u32.u64 %0, t; }" : "=r"(a) : "l"(p));
    return a;
}
__device__ __forceinline__ void ldsm4(uint32_t* r, uint32_t addr) {
    asm volatile("ldmatrix.sync.aligned.m8n8.x4.shared.b16 {%0,%1,%2,%3}, [%4];"
        : "=r"(r[0]), "=r"(r[1]), "=r"(r[2]), "=r"(r[3]) : "r"(addr));
}
__device__ __forceinline__ void mma16816(float* d, const uint32_t* a, const uint32_t* b) {
    asm volatile("mma.sync.aligned.m16n8k16.row.col.f32.bf16.bf16.f32 "
        "{%0,%1,%2,%3}, {%4,%5,%6,%7}, {%8,%9}, {%0,%1,%2,%3};"
        : "+f"(d[0]), "+f"(d[1]), "+f"(d[2]), "+f"(d[3])
        : "r"(a[0]), "r"(a[1]), "r"(a[2]), "r"(a[3]), "r"(b[0]), "r"(b[1]));
}

// ------------------------- prep kernels -------------------------------------
__global__ void zero_planes_kernel() {
    int i = blockIdx.x*256 + threadIdx.x;
    uint32_t* a = (uint32_t*)g_hhi;
    uint32_t* b = (uint32_t*)g_hlo;
    if (i < 2*2*PB_*H_/2) { a[i] = 0u; b[i] = 0u; }
}
__global__ void prep_w_kernel(const float* __restrict__ wa, const float* __restrict__ wb) {
    int idx = blockIdx.x*256 + threadIdx.x;         // 2*768*256
    int k = idx & 255;
    int r = (idx >> 8) % 768;
    int gru = idx / (768*256);
    float v = (gru ? wb : wa)[r*256 + k];
    __nv_bfloat16 hi = __float2bfloat16(v);
    g_whi[gru][r*256 + k] = hi;
    g_wlo[gru][r*256 + k] = __float2bfloat16(v - __bfloat162float(hi));
}
__global__ void prep_bw_kernel(const float* __restrict__ bw) {
    int idx = blockIdx.x*256 + threadIdx.x;         // 256*256
    float v = bw[idx];
    __nv_bfloat16 hi = __float2bfloat16(v);
    g_bwhi[idx] = hi;
    g_bwlo[idx] = __float2bfloat16(v - __bfloat162float(hi));
}
__global__ void prep_mt_kernel(const float* __restrict__ emb_w, const float* __restrict__ out_w) {
    int idx = blockIdx.x*256 + threadIdx.x;         // 256*256, [i][e]
    int i = idx >> 8, e = idx & 255;
    float v = out_w[e] * emb_w[e*256 + i];
    __nv_bfloat16 hi = __float2bfloat16(v);
    g_mthi[idx] = hi;
    g_mtlo[idx] = __float2bfloat16(v - __bfloat162float(hi));
}

// ------------------------- fp32 SGEMM (emb / gx) ----------------------------
__device__ __forceinline__ const float* arow_ptr(const float* A, int m, int xmode) {
    if (xmode) { int t = m >> 5, b = m & 31; return A + ((size_t)b*T_ + t)*E_; }
    return A + (size_t)m*E_;
}
__global__ void __launch_bounds__(256, 2)
sgemm128(const float* __restrict__ A, const float* __restrict__ Bt,
         const float* __restrict__ bias, float* __restrict__ C,
         int N, int act, int xmode) {
    __shared__ float As[2][8][128];
    __shared__ float Bs[2][8][128];
    const int tid = threadIdx.x;
    const int m0 = blockIdx.x * 128, n0 = blockIdx.y * 128;
    const int tx = tid & 15, ty = tid >> 4;
    const int lr = tid >> 1;
    const int ks = (tid & 1) * 4;
    const float* pA = arow_ptr(A, m0 + lr, xmode) + ks;
    const float* pB = Bt + (size_t)(n0 + lr) * 256 + ks;
    float acc[2][2][4][4] = {};
    float4 va = *(const float4*)pA;
    float4 vb = *(const float4*)pB;
    {
        const float* f = (const float*)&va;
#pragma unroll
        for (int j = 0; j < 4; j++) As[0][ks+j][lr] = f[j];
        f = (const float*)&vb;
#pragma unroll
        for (int j = 0; j < 4; j++) Bs[0][ks+j][lr] = f[j];
    }
    __syncthreads();
    int buf = 0;
#pragma unroll 1
    for (int c = 0; c < 32; c++) {
        if (c < 31) {
            int off = (c+1)*8;
            va = *(const float4*)(pA + off);
            vb = *(const float4*)(pB + off);
        }
#pragma unroll
        for (int kk = 0; kk < 8; kk++) {
            float4 a0 = *(const float4*)&As[buf][kk][ty*4];
            float4 a1 = *(const float4*)&As[buf][kk][ty*4 + 64];
            float4 b0 = *(const float4*)&Bs[buf][kk][tx*4];
            float4 b1 = *(const float4*)&Bs[buf][kk][tx*4 + 64];
            float aa[2][4] = {{a0.x,a0.y,a0.z,a0.w},{a1.x,a1.y,a1.z,a1.w}};
            float bb[2][4] = {{b0.x,b0.y,b0.z,b0.w},{b1.x,b1.y,b1.z,b1.w}};
#pragma unroll
            for (int rh = 0; rh < 2; rh++)
#pragma unroll
            for (int i = 0; i < 4; i++)
#pragma unroll
            for (int ch = 0; ch < 2; ch++)
#pragma unroll
            for (int j = 0; j < 4; j++)
                acc[rh][ch][i][j] = fmaf(aa[rh][i], bb[ch][j], acc[rh][ch][i][j]);
        }
        if (c < 31) {
            int nb = buf ^ 1;
            const float* f = (const float*)&va;
#pragma unroll
            for (int j = 0; j < 4; j++) As[nb][ks+j][lr] = f[j];
            f = (const float*)&vb;
#pragma unroll
            for (int j = 0; j < 4; j++) Bs[nb][ks+j][lr] = f[j];
            __syncthreads();
            buf = nb;
        }
    }
#pragma unroll
    for (int rh = 0; rh < 2; rh++)
#pragma unroll
    for (int i = 0; i < 4; i++) {
        int m = m0 + rh*64 + ty*4 + i;
#pragma unroll
        for (int ch = 0; ch < 2; ch++) {
            int n = n0 + ch*64 + tx*4;
            float4 v;
            v.x = acc[rh][ch][i][0]; v.y = acc[rh][ch][i][1];
            v.z = acc[rh][ch][i][2]; v.w = acc[rh][ch][i][3];
            if (bias) {
                float4 bz = *(const float4*)&bias[n];
                v.x += bz.x; v.y += bz.y; v.z += bz.z; v.w += bz.w;
            }
            if (act == 1) { v.x = tanhf(v.x); v.y = tanhf(v.y); v.z = tanhf(v.z); v.w = tanhf(v.w); }
            *(float4*)&C[(size_t)m*N + n] = v;
        }
    }
}

// ------------------------- mma GRU step -------------------------------------
// 512 thr, CTA = 128 rows x (3 gates x 64 cols). Grid (rowblks, 4, 2).
__global__ void __launch_bounds__(512, 1)
gru_step_mma(int k, int offk, int par,
             const float* __restrict__ bhh_a, const float* __restrict__ bhh_b) {
    __shared__ __align__(16) __nv_bfloat16 sA[2][128*PITCH];
    __shared__ __align__(16) __nv_bfloat16 sB[2][192*PITCH];
    const int tid = threadIdx.x, lane = tid & 31, wid = tid >> 5;
    const int wm = wid & 3, wn = wid >> 2;
    const int gru = blockIdx.z, cb = blockIdx.y;
    const int rowbase = k*32 + blockIdx.x*128;

    const __nv_bfloat16* Hhi = g_hhi[gru][par];
    const __nv_bfloat16* Hlo = g_hlo[gru][par];
    const __nv_bfloat16* Whi = g_whi[gru];
    const __nv_bfloat16* Wlo = g_wlo[gru];

    float acc[3][2][2][4] = {};

    const int a_r = lane & 15, a_c = ((lane >> 4) & 1) * 8;
    const int b_r = (lane & 7) + ((lane >> 4) & 1) * 8, b_c = lane & 8;
    uint32_t aoff[2][2], boff[2][3];
#pragma unroll
    for (int p = 0; p < 2; p++) {
        uint32_t ab = smem_u32(&sA[p][0]);
        uint32_t bb = smem_u32(&sB[p][0]);
#pragma unroll
        for (int i = 0; i < 2; i++)
            aoff[p][i] = ab + ((wm*32 + i*16 + a_r)*PITCH + a_c)*2;
#pragma unroll
        for (int g = 0; g < 3; g++)
            boff[p][g] = bb + ((g*64 + wn*16 + b_r)*PITCH + b_c)*2;
    }

#pragma unroll 1
    for (int c = 0; c < 16; c++) {
        int k0 = c*16;
        // A: 128 rows x 16 bf16 x 2 planes -> 512 uint4
#pragma unroll
        for (int it = tid; it < 512; it += 512) {
            int plane = it >> 8, r = (it >> 1) & 127, q = it & 1;
            int grow = rowbase + r; if (grow > PB_-1) grow = PB_-1;
            const uint4 v = *(const uint4*)((plane ? Hlo : Hhi) + (size_t)grow*H_ + k0 + q*8);
            *(uint4*)&sA[plane][r*PITCH + q*8] = v;
        }
        // B: 192 rows x 16 x 2 planes -> 768 uint4
#pragma unroll
        for (int it = tid; it < 768; it += 512) {
            int plane = it >= 384 ? 1 : 0; int rq = it - plane*384;
            int r = rq >> 1, q = rq & 1;
            int g = r >> 6, col = cb*64 + (r & 63);
            const uint4 v = *(const uint4*)((plane ? Wlo : Whi) + (size_t)(g*256 + col)*H_ + k0 + q*8);
            *(uint4*)&sB[plane][r*PITCH + q*8] = v;
        }
        __syncthreads();
        uint32_t Ah[2][4], Al[2][4];
        ldsm4(Ah[0], aoff[0][0]); ldsm4(Ah[1], aoff[0][1]);
        ldsm4(Al[0], aoff[1][0]); ldsm4(Al[1], aoff[1][1]);
#pragma unroll
        for (int g = 0; g < 3; g++) {
            uint32_t Bh[4], Bl[4];
            ldsm4(Bh, boff[0][g]); ldsm4(Bl, boff[1][g]);
#pragma unroll
            for (int i = 0; i < 2; i++)
#pragma unroll
            for (int j = 0; j < 2; j++) {
                mma16816(acc[g][i][j], Ah[i], &Bh[j*2]);
                mma16816(acc[g][i][j], Ah[i], &Bl[j*2]);
                mma16816(acc[g][i][j], Al[i], &Bh[j*2]);
            }
        }
        __syncthreads();
    }

    // epilogue
    const float* bhh = gru ? bhh_b : bhh_a;
    const float* gx  = gru ? g_gxb : g_gxa;
    __nv_bfloat16* Hhi_n = g_hhi[gru][par^1];
    __nv_bfloat16* Hlo_n = g_hlo[gru][par^1];
    const int g8 = lane >> 2, t2 = (lane & 3)*2;
#pragma unroll
    for (int i = 0; i < 2; i++)
#pragma unroll
    for (int half = 0; half < 2; half++) {
        int lr = wm*32 + i*16 + g8 + half*8;
        int grow = rowbase + lr;
        if (grow >= PB_) continue;
        int gxrow = grow - k*32;
        const float* gxr = gx + (size_t)gxrow*(3*H_);
        size_t prow = (size_t)offk + gxrow;
#pragma unroll
        for (int j = 0; j < 2; j++) {
            int cc = cb*64 + wn*16 + j*8 + t2;
            float hn2[2];
#pragma unroll
            for (int u = 0; u < 2; u++) {
                int ci = cc + u;
                int ai = half*2 + u;
                float rp = acc[0][i][j][ai] + bhh[ci]        + gxr[ci];
                float zp = acc[1][i][j][ai] + bhh[H_+ci]     + gxr[H_+ci];
                float np = acc[2][i][j][ai] + bhh[2*H_+ci];
                float r = 1.f/(1.f + expf(-rp));
                float z = 1.f/(1.f + expf(-zp));
                float n = tanhf(gxr[2*H_+ci] + r*np);
                float hold = __bfloat162float(Hhi[(size_t)grow*H_ + ci])
                           + __bfloat162float(Hlo[(size_t)grow*H_ + ci]);
                hn2[u] = (1.f - z)*n + z*hold;
            }
            __nv_bfloat162 hi2, lo2;
            hi2.x = __float2bfloat16(hn2[0]); hi2.y = __float2bfloat16(hn2[1]);
            lo2.x = __float2bfloat16(hn2[0] - __bfloat162float(hi2.x));
            lo2.y = __float2bfloat16(hn2[1] - __bfloat162float(hi2.y));
            *(__nv_bfloat162*)&Hhi_n[(size_t)grow*H_ + cc] = hi2;
            *(__nv_bfloat162*)&Hlo_n[(size_t)grow*H_ + cc] = lo2;
            if (gru == 0) {
                float2 f2; f2.x = 0.5f*hn2[0]; f2.y = 0.5f*hn2[1];
                *(float2*)&g_fa[prow*H_ + cc] = f2;
            } else {
                float f0 = 0.5f*hn2[0], f1 = 0.5f*hn2[1];
                __nv_bfloat162 fh, fl;
                fh.x = __float2bfloat16(f0); fh.y = __float2bfloat16(f1);
                fl.x = __float2bfloat16(f0 - __bfloat162float(fh.x));
                fl.y = __float2bfloat16(f1 - __bfloat162float(fh.y));
                *(__nv_bfloat162*)&g_fbhi[prow*H_ + cc] = fh;
                *(__nv_bfloat162*)&g_fblo[prow*H_ + cc] = fl;
            }
        }
    }
}

// ------------------------- mma dense GEMM (M x 256, K=256) ------------------
// 512 thr, CTA = 128 rows x 128 cols. Grid (M/128, 2).
__global__ void __launch_bounds__(512, 1)
dense_mma(const __nv_bfloat16* __restrict__ Ahi, const __nv_bfloat16* __restrict__ Alo,
          const __nv_bfloat16* __restrict__ Bthi, const __nv_bfloat16* __restrict__ Btlo,
          const float* __restrict__ bias, int act, float* __restrict__ outf,
          __nv_bfloat16* __restrict__ Phi, __nv_bfloat16* __restrict__ Plo) {
    __shared__ __align__(16) __nv_bfloat16 sA[2][128*PITCH];
    __shared__ __align__(16) __nv_bfloat16 sB[2][128*PITCH];
    const int tid = threadIdx.x, lane = tid & 31, wid = tid >> 5;
    const int wm = wid & 3, wn = wid >> 2;
    const int cb = blockIdx.y;
    const int rowbase = blockIdx.x * 128;

    float acc[2][4][4] = {};

    const int a_r = lane & 15, a_c = ((lane >> 4) & 1) * 8;
    const int b_r = (lane & 7) + ((lane >> 4) & 1) * 8, b_c = lane & 8;
    uint32_t aoff[2][2], boff[2][2];
#pragma unroll
    for (int p = 0; p < 2; p++) {
        uint32_t ab = smem_u32(&sA[p][0]);
        uint32_t bb = smem_u32(&sB[p][0]);
#pragma unroll
        for (int i = 0; i < 2; i++)
            aoff[p][i] = ab + ((wm*32 + i*16 + a_r)*PITCH + a_c)*2;
#pragma unroll
        for (int h2 = 0; h2 < 2; h2++)
            boff[p][h2] = bb + ((wn*32 + h2*16 + b_r)*PITCH + b_c)*2;
    }

#pragma unroll 1
    for (int c = 0; c < 16; c++) {
        int k0 = c*16;
#pragma unroll
        for (int it = tid; it < 512; it += 512) {
            int plane = it >> 8, r = (it >> 1) & 127, q = it & 1;
            const uint4 v = *(const uint4*)((plane ? Alo : Ahi) + (size_t)(rowbase + r)*H_ + k0 + q*8);
            *(uint4*)&sA[plane][r*PITCH + q*8] = v;
        }
#pragma unroll
        for (int it = tid; it < 512; it += 512) {
            int plane = it >> 8, r = (it >> 1) & 127, q = it & 1;
            const uint4 v = *(const uint4*)((plane ? Btlo : Bthi) + (size_t)(cb*128 + r)*H_ + k0 + q*8);
            *(uint4*)&sB[plane][r*PITCH + q*8] = v;
        }
        __syncthreads();
        uint32_t Ah[2][4], Al[2][4], Bh[8], Bl[8];
        ldsm4(Ah[0], aoff[0][0]); ldsm4(Ah[1], aoff[0][1]);
        ldsm4(Al[0], aoff[1][0]); ldsm4(Al[1], aoff[1][1]);
        ldsm4(Bh,   boff[0][0]); ldsm4(Bh+4, boff[0][1]);
        ldsm4(Bl,   boff[1][0]); ldsm4(Bl+4, boff[1][1]);
#pragma unroll
        for (int i = 0; i < 2; i++)
#pragma unroll
        for (int j = 0; j < 4; j++) {
            mma16816(acc[i][j], Ah[i], &Bh[j*2]);
            mma16816(acc[i][j], Ah[i], &Bl[j*2]);
            mma16816(acc[i][j], Al[i], &Bh[j*2]);
        }
        __syncthreads();
    }

    const int g8 = lane >> 2, t2 = (lane & 3)*2;
#pragma unroll
    for (int i = 0; i < 2; i++)
#pragma unroll
    for (int half = 0; half < 2; half++) {
        int grow = rowbase + wm*32 + i*16 + g8 + half*8;
#pragma unroll
        for (int j = 0; j < 4; j++) {
            int cc = cb*128 + wn*32 + j*8 + t2;
            float v0 = acc[i][j][half*2 + 0];
            float v1 = acc[i][j][half*2 + 1];
            if (bias) { v0 += bias[cc]; v1 += bias[cc+1]; }
            if (act == 1) { v0 = tanhf(v0); v1 = tanhf(v1); }
            float2 f2; f2.x = v0; f2.y = v1;
            *(float2*)&outf[(size_t)grow*E_ + cc] = f2;
            if (Phi) {
                __nv_bfloat162 hi2, lo2;
                hi2.x = __float2bfloat16(v0); hi2.y = __float2bfloat16(v1);
                lo2.x = __float2bfloat16(v0 - __bfloat162float(hi2.x));
                lo2.y = __float2bfloat16(v1 - __bfloat162float(hi2.y));
                *(__nv_bfloat162*)&Phi[(size_t)grow*E_ + cc] = hi2;
                *(__nv_bfloat162*)&Plo[(size_t)grow*E_ + cc] = lo2;
            }
        }
    }
}

// ------------------------- pre / alpha / reduce -----------------------------
__global__ void pre_kernel(const float* __restrict__ alpha_w,
                           const float* __restrict__ alpha_b) {
    int gw = (blockIdx.x*blockDim.x + threadIdx.x) >> 5;
    int lane = threadIdx.x & 31;
    if (gw >= NPACK_) return;
    int k = 0, off = 0;
    while (k < 62 && off + (63-k)*32 <= gw) { off += (63-k)*32; k++; }
    int l = gw - off;
    int t = l >> 5, b = l & 31;
    int p = k + t;
    const float* fa = g_fa + (size_t)gw*H_;
    float s = 0.f;
    for (int e = lane; e < H_; e += 32) s += fa[e]*alpha_w[e];
#pragma unroll
    for (int o=16;o;o>>=1) s += __shfl_xor_sync(0xffffffffu, s, o);
    if (lane == 0) g_pre[(p*T_ + t)*B_ + b] = s + alpha_b[0];
}

__global__ void alpha_kernel() {
    int gw = (blockIdx.x*blockDim.x + threadIdx.x) >> 5;
    int lane = threadIdx.x & 31;
    if (gw >= PB_) return;
    int p = gw >> 5, b = gw & 31;
    float v0 = (lane      <= p) ? g_pre[(p*T_+lane   )*B_+b] : -1e30f;
    float v1 = (lane + 32 <= p) ? g_pre[(p*T_+lane+32)*B_+b] : -1e30f;
    float m = fmaxf(v0, v1);
#pragma unroll
    for (int o=16;o;o>>=1) m = fmaxf(m, __shfl_xor_sync(0xffffffffu, m, o));
    float e0 = (lane      <= p) ? expf(v0-m) : 0.f;
    float e1 = (lane + 32 <= p) ? expf(v1-m) : 0.f;
    float s = e0 + e1;
#pragma unroll
    for (int o=16;o;o>>=1) s += __shfl_xor_sync(0xffffffffu, s, o);
    float inv = 1.f/s;
    g_alpha[(p*T_+lane   )*B_+b] = e0*inv;
    g_alpha[(p*T_+lane+32)*B_+b] = e1*inv;
}

__global__ void reduce_kernel(const float* __restrict__ x,
                              const float* __restrict__ out_w,
                              const float* __restrict__ out_b,
                              float* __restrict__ out) {
    int pb = blockIdx.x;
    int p = pb >> 5, b = pb & 31;
    int e = threadIdx.x;
    float cc = 0.f, gg = 0.f;
    for (int t = 0; t <= p; t++) {
        float a = g_alpha[(p*T_+t)*B_+b];
        int kk = p - t;
        int offk = 32*(63*kk - (kk*(kk-1))/2);
        size_t prow = (size_t)offk + t*32 + b;
        cc += a * g_beta [prow*E_ + e] * g_emb[((size_t)(t*B_+b))*E_ + e];
        gg += a * g_ebeta[prow*E_ + e] * x[((size_t)b*T_ + t)*E_ + e];
    }
    out[B_*P_ + ((size_t)(b*P_+p))*E_ + e] = gg / (float)(p+1);
    __shared__ float red[256];
    red[e] = cc * out_w[e];
    __syncthreads();
    for (int s2=128; s2; s2>>=1) { if (e < s2) red[e] += red[e+s2]; __syncthreads(); }
    if (e == 0) out[b*P_ + p] = red[0] + out_b[0];
}

// ------------------------- launch -------------------------------------------
extern "C" void kernel_launch(void* const* d_in, const int* in_sizes, int n_in,
                              void* d_out, int out_size) {
    (void)in_sizes; (void)n_in; (void)out_size;
    const float* x       = (const float*)d_in[0];
    const float* emb_w   = (const float*)d_in[1];
    const float* emb_b   = (const float*)d_in[2];
    const float* a_wih   = (const float*)d_in[3];
    const float* a_whh   = (const float*)d_in[4];
    const float* a_bih   = (const float*)d_in[5];
    const float* a_bhh   = (const float*)d_in[6];
    const float* b_wih   = (const float*)d_in[7];
    const float* b_whh   = (const float*)d_in[8];
    const float* b_bih   = (const float*)d_in[9];
    const float* b_bhh   = (const float*)d_in[10];
    const float* alpha_w = (const float*)d_in[11];
    const float* alpha_b = (const float*)d_in[12];
    const float* beta_w  = (const float*)d_in[13];
    const float* beta_b  = (const float*)d_in[14];
    const float* out_w   = (const float*)d_in[15];
    const float* out_b   = (const float*)d_in[16];
    float* out = (float*)d_out;

    float *p_emb=0, *p_gxa=0, *p_gxb=0, *p_beta=0, *p_ebeta=0;
    __nv_bfloat16 *p_fbhi=0, *p_fblo=0, *p_bwhi=0, *p_bwlo=0;
    __nv_bfloat16 *p_mthi=0, *p_mtlo=0, *p_bhi=0, *p_blo=0;
    cudaGetSymbolAddress((void**)&p_emb,   g_emb);
    cudaGetSymbolAddress((void**)&p_gxa,   g_gxa);
    cudaGetSymbolAddress((void**)&p_gxb,   g_gxb);
    cudaGetSymbolAddress((void**)&p_beta,  g_beta);
    cudaGetSymbolAddress((void**)&p_ebeta, g_ebeta);
    cudaGetSymbolAddress((void**)&p_fbhi,  g_fbhi);
    cudaGetSymbolAddress((void**)&p_fblo,  g_fblo);
    cudaGetSymbolAddress((void**)&p_bwhi,  g_bwhi);
    cudaGetSymbolAddress((void**)&p_bwlo,  g_bwlo);
    cudaGetSymbolAddress((void**)&p_mthi,  g_mthi);
    cudaGetSymbolAddress((void**)&p_mtlo,  g_mtlo);
    cudaGetSymbolAddress((void**)&p_bhi,   g_betahi);
    cudaGetSymbolAddress((void**)&p_blo,   g_betalo);

    zero_planes_kernel<<<(2*2*PB_*H_/2 + 255)/256, 256>>>();
    prep_w_kernel<<<(2*768*256)/256, 256>>>(a_whh, b_whh);
    prep_bw_kernel<<<256, 256>>>(beta_w);
    prep_mt_kernel<<<256, 256>>>(emb_w, out_w);

    sgemm128<<<dim3((T_*B_)/128, E_/128), 256>>>(x, emb_w, emb_b, p_emb, E_, 0, 1);
    sgemm128<<<dim3((T_*B_)/128, (3*H_)/128), 256>>>(p_emb, a_wih, a_bih, p_gxa, 3*H_, 0, 0);
    sgemm128<<<dim3((T_*B_)/128, (3*H_)/128), 256>>>(p_emb, b_wih, b_bih, p_gxb, 3*H_, 0, 0);

    int offk = 0, par = 0;
    for (int k = 0; k < 63; k++) {
        int active = (63-k)*32;
        int nb = (active + 127)/128;
        gru_step_mma<<<dim3(nb, 4, 2), 512>>>(k, offk, par, a_bhh, b_bhh);
        offk += active;
        par ^= 1;
    }

    pre_kernel<<<(NPACK_*32 + 255)/256, 256>>>(alpha_w, alpha_b);
    alpha_kernel<<<(PB_*32 + 255)/256, 256>>>();

    dense_mma<<<dim3(NPACK_/128, 2), 512>>>(p_fbhi, p_fblo, p_bwhi, p_bwlo,
                                            beta_b, 1, p_beta, p_bhi, p_blo);
    dense_mma<<<dim3(NPACK_/128, 2), 512>>>(p_bhi, p_blo, p_mthi, p_mtlo,
                                            (const float*)0, 0, p_ebeta,
                                            (__nv_bfloat16*)0, (__nv_bfloat16*)0);

    reduce_kernel<<<PB_, 256>>>(x, out_w, out_b, out);
}

// round 5
// speedup vs baseline: 1.4617x; 1.2100x over previous
#include <cuda_runtime.h>
#include <cuda_bf16.h>
#include <math.h>
#include <stdint.h>

#define B_ 32
#define T_ 64
#define E_ 256
#define H_ 256
#define P_ 63
#define PB_ 2016
#define NPACK_ 64512
#define PITCH 24   // bf16 elements per A smem row (16 data + 8 pad)

#define NCTA_PERS 128
#define SMEM_W_BYTES 196608            // 16 chunks * 2 planes * 192 rows * 32B
#define SMEM_A_OFF   196608            // A buffers start
#define SMEM_TOTAL_PERS (196608 + 24576)

// ------------------------- scratch (device globals) -------------------------
__device__ float g_emb[T_*B_*E_];
__device__ float g_gxa[T_*B_*3*H_];
__device__ float g_gxb[T_*B_*3*H_];
__device__ __nv_bfloat16 g_hhi[2][2][PB_*H_];   // [gru][parity]
__device__ __nv_bfloat16 g_hlo[2][2][PB_*H_];
__device__ __nv_bfloat16 g_whi[2][3*H_*H_];     // recurrent weights, hi plane
__device__ __nv_bfloat16 g_wlo[2][3*H_*H_];
__device__ __nv_bfloat16 g_bwhi[E_*H_];
__device__ __nv_bfloat16 g_bwlo[E_*H_];
__device__ __nv_bfloat16 g_mthi[E_*E_];
__device__ __nv_bfloat16 g_mtlo[E_*E_];
__device__ float g_fa[(size_t)NPACK_*H_];
__device__ __nv_bfloat16 g_fbhi[(size_t)NPACK_*H_];
__device__ __nv_bfloat16 g_fblo[(size_t)NPACK_*H_];
__device__ float g_beta[(size_t)NPACK_*E_];
__device__ __nv_bfloat16 g_betahi[(size_t)NPACK_*E_];
__device__ __nv_bfloat16 g_betalo[(size_t)NPACK_*E_];
__device__ float g_ebeta[(size_t)NPACK_*E_];
__device__ float g_pre[P_*T_*B_];
__device__ float g_alpha[P_*T_*B_];
__device__ unsigned g_bar;

// ------------------------- helpers ------------------------------------------
__device__ __forceinline__ uint32_t smem_u32(const void* p) {
    uint32_t a;
    asm("{ .reg .u64 t; cvta.to.shared.u64 t, %1; cvt.u32.u64 %0, t; }" : "=r"(a) : "l"(p));
    return a;
}
__device__ __forceinline__ void ldsm4(uint32_t* r, uint32_t addr) {
    asm volatile("ldmatrix.sync.aligned.m8n8.x4.shared.b16 {%0,%1,%2,%3}, [%4];"
        : "=r"(r[0]), "=r"(r[1]), "=r"(r[2]), "=r"(r[3]) : "r"(addr));
}
__device__ __forceinline__ void mma16816(float* d, const uint32_t* a, const uint32_t* b) {
    asm volatile("mma.sync.aligned.m16n8k16.row.col.f32.bf16.bf16.f32 "
        "{%0,%1,%2,%3}, {%4,%5,%6,%7}, {%8,%9}, {%0,%1,%2,%3};"
        : "+f"(d[0]), "+f"(d[1]), "+f"(d[2]), "+f"(d[3])
        : "r"(a[0]), "r"(a[1]), "r"(a[2]), "r"(a[3]), "r"(b[0]), "r"(b[1]));
}
#define CP_ASYNC16(dst, src) \
    asm volatile("cp.async.cg.shared.global [%0], [%1], 16;" :: "r"(dst), "l"(src))
#define CP_COMMIT() asm volatile("cp.async.commit_group;")
#define CP_WAIT1()  asm volatile("cp.async.wait_group 1;")
#define CP_WAIT0()  asm volatile("cp.async.wait_group 0;")

// ------------------------- prep kernels -------------------------------------
__global__ void zero_planes_kernel() {
    int i = blockIdx.x*256 + threadIdx.x;
    uint32_t* a = (uint32_t*)g_hhi;
    uint32_t* b = (uint32_t*)g_hlo;
    if (i < 2*2*PB_*H_/2) { a[i] = 0u; b[i] = 0u; }
    if (i == 0) g_bar = 0u;
}
__global__ void prep_w_kernel(const float* __restrict__ wa, const float* __restrict__ wb) {
    int idx = blockIdx.x*256 + threadIdx.x;
    int k = idx & 255;
    int r = (idx >> 8) % 768;
    int gru = idx / (768*256);
    float v = (gru ? wb : wa)[r*256 + k];
    __nv_bfloat16 hi = __float2bfloat16(v);
    g_whi[gru][r*256 + k] = hi;
    g_wlo[gru][r*256 + k] = __float2bfloat16(v - __bfloat162float(hi));
}
__global__ void prep_bw_kernel(const float* __restrict__ bw) {
    int idx = blockIdx.x*256 + threadIdx.x;
    float v = bw[idx];
    __nv_bfloat16 hi = __float2bfloat16(v);
    g_bwhi[idx] = hi;
    g_bwlo[idx] = __float2bfloat16(v - __bfloat162float(hi));
}
__global__ void prep_mt_kernel(const float* __restrict__ emb_w, const float* __restrict__ out_w) {
    int idx = blockIdx.x*256 + threadIdx.x;
    int i = idx >> 8, e = idx & 255;
    float v = out_w[e] * emb_w[e*256 + i];
    __nv_bfloat16 hi = __float2bfloat16(v);
    g_mthi[idx] = hi;
    g_mtlo[idx] = __float2bfloat16(v - __bfloat162float(hi));
}

// ------------------------- fp32 SGEMM (emb / gx) ----------------------------
__device__ __forceinline__ const float* arow_ptr(const float* A, int m, int xmode) {
    if (xmode) { int t = m >> 5, b = m & 31; return A + ((size_t)b*T_ + t)*E_; }
    return A + (size_t)m*E_;
}
__global__ void __launch_bounds__(256, 2)
sgemm128(const float* __restrict__ A, const float* __restrict__ Bt,
         const float* __restrict__ bias, float* __restrict__ C,
         int N, int act, int xmode) {
    __shared__ float As[2][8][128];
    __shared__ float Bs[2][8][128];
    const int tid = threadIdx.x;
    const int m0 = blockIdx.x * 128, n0 = blockIdx.y * 128;
    const int tx = tid & 15, ty = tid >> 4;
    const int lr = tid >> 1;
    const int ks = (tid & 1) * 4;
    const float* pA = arow_ptr(A, m0 + lr, xmode) + ks;
    const float* pB = Bt + (size_t)(n0 + lr) * 256 + ks;
    float acc[2][2][4][4] = {};
    float4 va = *(const float4*)pA;
    float4 vb = *(const float4*)pB;
    {
        const float* f = (const float*)&va;
#pragma unroll
        for (int j = 0; j < 4; j++) As[0][ks+j][lr] = f[j];
        f = (const float*)&vb;
#pragma unroll
        for (int j = 0; j < 4; j++) Bs[0][ks+j][lr] = f[j];
    }
    __syncthreads();
    int buf = 0;
#pragma unroll 1
    for (int c = 0; c < 32; c++) {
        if (c < 31) {
            int off = (c+1)*8;
            va = *(const float4*)(pA + off);
            vb = *(const float4*)(pB + off);
        }
#pragma unroll
        for (int kk = 0; kk < 8; kk++) {
            float4 a0 = *(const float4*)&As[buf][kk][ty*4];
            float4 a1 = *(const float4*)&As[buf][kk][ty*4 + 64];
            float4 b0 = *(const float4*)&Bs[buf][kk][tx*4];
            float4 b1 = *(const float4*)&Bs[buf][kk][tx*4 + 64];
            float aa[2][4] = {{a0.x,a0.y,a0.z,a0.w},{a1.x,a1.y,a1.z,a1.w}};
            float bb[2][4] = {{b0.x,b0.y,b0.z,b0.w},{b1.x,b1.y,b1.z,b1.w}};
#pragma unroll
            for (int rh = 0; rh < 2; rh++)
#pragma unroll
            for (int i = 0; i < 4; i++)
#pragma unroll
            for (int ch = 0; ch < 2; ch++)
#pragma unroll
            for (int j = 0; j < 4; j++)
                acc[rh][ch][i][j] = fmaf(aa[rh][i], bb[ch][j], acc[rh][ch][i][j]);
        }
        if (c < 31) {
            int nb = buf ^ 1;
            const float* f = (const float*)&va;
#pragma unroll
            for (int j = 0; j < 4; j++) As[nb][ks+j][lr] = f[j];
            f = (const float*)&vb;
#pragma unroll
            for (int j = 0; j < 4; j++) Bs[nb][ks+j][lr] = f[j];
            __syncthreads();
            buf = nb;
        }
    }
#pragma unroll
    for (int rh = 0; rh < 2; rh++)
#pragma unroll
    for (int i = 0; i < 4; i++) {
        int m = m0 + rh*64 + ty*4 + i;
#pragma unroll
        for (int ch = 0; ch < 2; ch++) {
            int n = n0 + ch*64 + tx*4;
            float4 v;
            v.x = acc[rh][ch][i][0]; v.y = acc[rh][ch][i][1];
            v.z = acc[rh][ch][i][2]; v.w = acc[rh][ch][i][3];
            if (bias) {
                float4 bz = *(const float4*)&bias[n];
                v.x += bz.x; v.y += bz.y; v.z += bz.z; v.w += bz.w;
            }
            if (act == 1) { v.x = tanhf(v.x); v.y = tanhf(v.y); v.z = tanhf(v.z); v.w = tanhf(v.w); }
            *(float4*)&C[(size_t)m*N + n] = v;
        }
    }
}

// ------------------------- persistent GRU recurrence ------------------------
// Grid: exactly 128 CTAs x 512 threads. CTA = (gru, cb, rb).
// Weights resident in smem all 63 steps; A (h-state) cp.async double-buffered.
__global__ void __launch_bounds__(512, 1)
gru_persistent(const float* __restrict__ bhh_a, const float* __restrict__ bhh_b) {
    extern __shared__ __align__(16) unsigned char smem[];
    const int tid = threadIdx.x, lane = tid & 31, wid = tid >> 5;
    const int wm = wid & 3, wn = wid >> 2;
    const int gid = blockIdx.x;
    const int gru = gid & 1, cb = (gid >> 1) & 3, rb = gid >> 3;
    const uint32_t sbase = smem_u32(smem);

    // ---- one-time: load weight slice (3 gates x 64 cols, K=256, 2 planes) ----
    {
        const __nv_bfloat16* Whi = g_whi[gru];
        const __nv_bfloat16* Wlo = g_wlo[gru];
        for (int it = tid; it < 12288; it += 512) {
            int q = it & 1;
            int r = (it >> 1) % 192;
            int t3 = (it >> 1) / 192;     // 0..31
            int p = t3 & 1;
            int c = t3 >> 1;              // 0..15
            int R = (r >> 6)*256 + cb*64 + (r & 63);
            const __nv_bfloat16* src = (p ? Wlo : Whi) + (size_t)R*256 + c*16 + q*8;
            *(uint4*)(smem + c*12288 + p*6144 + r*32 + q*16) = *(const uint4*)src;
        }
    }
    __syncthreads();

    // ---- per-lane ldmatrix offsets ----
    const int a_r = lane & 15, a_c = ((lane >> 4) & 1) * 8;
    const int b_r = (lane & 7) + ((lane >> 4) & 1) * 8, b_c16 = (lane & 8) * 2;
    uint32_t abase[2][2][2];   // [buf][plane][i]
#pragma unroll
    for (int bf = 0; bf < 2; bf++)
#pragma unroll
    for (int p = 0; p < 2; p++)
#pragma unroll
    for (int i = 0; i < 2; i++)
        abase[bf][p][i] = sbase + SMEM_A_OFF + bf*12288u + p*6144u
                        + (uint32_t)((wm*32 + i*16 + a_r)*48 + a_c*2);
    uint32_t wboff[2][3];      // [plane][gate]
#pragma unroll
    for (int p = 0; p < 2; p++)
#pragma unroll
    for (int g = 0; g < 3; g++)
        wboff[p][g] = (uint32_t)(p*6144 + (g*64 + wn*16 + b_r)*32 + b_c16);

    const float* bhh = gru ? bhh_b : bhh_a;
    const float* gx  = gru ? g_gxb : g_gxa;
    const int st_q = tid & 1, st_r = (tid >> 1) & 127, st_p = tid >> 8;
    const uint32_t st_dst0 = sbase + SMEM_A_OFF + st_p*6144u + (uint32_t)(st_r*48 + st_q*16);

    const int g8 = lane >> 2, t2 = (lane & 3)*2;

#pragma unroll 1
    for (int step = 0; step < 63; step++) {
        const int par = step & 1;
        const int active = (63 - step)*32;
        if (rb*128 < active) {
            const __nv_bfloat16* Hhi = g_hhi[gru][par];
            const __nv_bfloat16* Hlo = g_hlo[gru][par];
            const int rowbase = step*32 + rb*128;
            int sgrow = rowbase + st_r; if (sgrow > PB_-1) sgrow = PB_-1;
            const __nv_bfloat16* st_src = (st_p ? Hlo : Hhi) + (size_t)sgrow*H_ + st_q*8;

            float acc[3][2][2][4] = {};
            // stage chunk 0
            CP_ASYNC16(st_dst0, st_src);
            CP_COMMIT();
#pragma unroll 1
            for (int c = 0; c < 16; c++) {
                if (c < 15) {
                    CP_ASYNC16(st_dst0 + (uint32_t)(((c+1)&1)*12288), st_src + (c+1)*16);
                    CP_COMMIT();
                    CP_WAIT1();
                } else {
                    CP_WAIT0();
                }
                __syncthreads();
                const int bf = c & 1;
                uint32_t Ah[2][4], Al[2][4];
                ldsm4(Ah[0], abase[bf][0][0]); ldsm4(Ah[1], abase[bf][0][1]);
                ldsm4(Al[0], abase[bf][1][0]); ldsm4(Al[1], abase[bf][1][1]);
                const uint32_t wbc = sbase + (uint32_t)(c*12288);
#pragma unroll
                for (int g = 0; g < 3; g++) {
                    uint32_t Bh[4], Bl[4];
                    ldsm4(Bh, wbc + wboff[0][g]);
                    ldsm4(Bl, wbc + wboff[1][g]);
#pragma unroll
                    for (int i = 0; i < 2; i++)
#pragma unroll
                    for (int j = 0; j < 2; j++) {
                        mma16816(acc[g][i][j], Ah[i], &Bh[j*2]);
                        mma16816(acc[g][i][j], Ah[i], &Bl[j*2]);
                        mma16816(acc[g][i][j], Al[i], &Bh[j*2]);
                    }
                }
                __syncthreads();
            }
            // ---- epilogue ----
            __nv_bfloat16* Hhi_n = g_hhi[gru][par^1];
            __nv_bfloat16* Hlo_n = g_hlo[gru][par^1];
            const size_t offk = (size_t)32*(63*step - (step*(step-1))/2);
#pragma unroll
            for (int i = 0; i < 2; i++)
#pragma unroll
            for (int half = 0; half < 2; half++) {
                int grow = rowbase + wm*32 + i*16 + g8 + half*8;
                if (grow >= PB_) continue;
                int gxrow = grow - step*32;
                const float* gxr = gx + (size_t)gxrow*(3*H_);
                size_t prow = offk + gxrow;
#pragma unroll
                for (int j = 0; j < 2; j++) {
                    int cc = cb*64 + wn*16 + j*8 + t2;
                    float2 gx_r = *(const float2*)&gxr[cc];
                    float2 gx_z = *(const float2*)&gxr[H_ + cc];
                    float2 gx_n = *(const float2*)&gxr[2*H_ + cc];
                    float2 bh_r = *(const float2*)&bhh[cc];
                    float2 bh_z = *(const float2*)&bhh[H_ + cc];
                    float2 bh_n = *(const float2*)&bhh[2*H_ + cc];
                    __nv_bfloat162 ho_hi = *(const __nv_bfloat162*)&Hhi[(size_t)grow*H_ + cc];
                    __nv_bfloat162 ho_lo = *(const __nv_bfloat162*)&Hlo[(size_t)grow*H_ + cc];
                    float hn2[2];
#pragma unroll
                    for (int u = 0; u < 2; u++) {
                        int ai = half*2 + u;
                        float rp = acc[0][i][j][ai] + (u ? bh_r.y : bh_r.x) + (u ? gx_r.y : gx_r.x);
                        float zp = acc[1][i][j][ai] + (u ? bh_z.y : bh_z.x) + (u ? gx_z.y : gx_z.x);
                        float np = acc[2][i][j][ai] + (u ? bh_n.y : bh_n.x);
                        float r = 1.f/(1.f + expf(-rp));
                        float z = 1.f/(1.f + expf(-zp));
                        float n = tanhf((u ? gx_n.y : gx_n.x) + r*np);
                        float hold = __bfloat162float(u ? ho_hi.y : ho_hi.x)
                                   + __bfloat162float(u ? ho_lo.y : ho_lo.x);
                        hn2[u] = (1.f - z)*n + z*hold;
                    }
                    __nv_bfloat162 hi2, lo2;
                    hi2.x = __float2bfloat16(hn2[0]); hi2.y = __float2bfloat16(hn2[1]);
                    lo2.x = __float2bfloat16(hn2[0] - __bfloat162float(hi2.x));
                    lo2.y = __float2bfloat16(hn2[1] - __bfloat162float(hi2.y));
                    *(__nv_bfloat162*)&Hhi_n[(size_t)grow*H_ + cc] = hi2;
                    *(__nv_bfloat162*)&Hlo_n[(size_t)grow*H_ + cc] = lo2;
                    if (gru == 0) {
                        float2 f2; f2.x = 0.5f*hn2[0]; f2.y = 0.5f*hn2[1];
                        *(float2*)&g_fa[prow*H_ + cc] = f2;
                    } else {
                        float f0 = 0.5f*hn2[0], f1 = 0.5f*hn2[1];
                        __nv_bfloat162 fh, fl;
                        fh.x = __float2bfloat16(f0); fh.y = __float2bfloat16(f1);
                        fl.x = __float2bfloat16(f0 - __bfloat162float(fh.x));
                        fl.y = __float2bfloat16(f1 - __bfloat162float(fh.y));
                        *(__nv_bfloat162*)&g_fbhi[prow*H_ + cc] = fh;
                        *(__nv_bfloat162*)&g_fblo[prow*H_ + cc] = fl;
                    }
                }
            }
        }
        // ---- grid-wide barrier ----
        __syncthreads();
        if (tid == 0) {
            __threadfence();
            atomicAdd(&g_bar, 1u);
            const unsigned target = (unsigned)NCTA_PERS*(step+1);
            unsigned v;
            do {
                asm volatile("ld.acquire.gpu.u32 %0, [%1];" : "=r"(v) : "l"(&g_bar));
            } while (v < target);
        }
        __syncthreads();
    }
}

// ------------------------- mma dense GEMM (M x 256, K=256) ------------------
__global__ void __launch_bounds__(512, 1)
dense_mma(const __nv_bfloat16* __restrict__ Ahi, const __nv_bfloat16* __restrict__ Alo,
          const __nv_bfloat16* __restrict__ Bthi, const __nv_bfloat16* __restrict__ Btlo,
          const float* __restrict__ bias, int act, float* __restrict__ outf,
          __nv_bfloat16* __restrict__ Phi, __nv_bfloat16* __restrict__ Plo) {
    __shared__ __align__(16) __nv_bfloat16 sA[2][128*PITCH];
    __shared__ __align__(16) __nv_bfloat16 sB[2][128*PITCH];
    const int tid = threadIdx.x, lane = tid & 31, wid = tid >> 5;
    const int wm = wid & 3, wn = wid >> 2;
    const int cb = blockIdx.y;
    const int rowbase = blockIdx.x * 128;

    float acc[2][4][4] = {};

    const int a_r = lane & 15, a_c = ((lane >> 4) & 1) * 8;
    const int b_r = (lane & 7) + ((lane >> 4) & 1) * 8, b_c = lane & 8;
    uint32_t aoff[2][2], boff[2][2];
#pragma unroll
    for (int p = 0; p < 2; p++) {
        uint32_t ab = smem_u32(&sA[p][0]);
        uint32_t bb = smem_u32(&sB[p][0]);
#pragma unroll
        for (int i = 0; i < 2; i++)
            aoff[p][i] = ab + ((wm*32 + i*16 + a_r)*PITCH + a_c)*2;
#pragma unroll
        for (int h2 = 0; h2 < 2; h2++)
            boff[p][h2] = bb + ((wn*32 + h2*16 + b_r)*PITCH + b_c)*2;
    }

#pragma unroll 1
    for (int c = 0; c < 16; c++) {
        int k0 = c*16;
#pragma unroll
        for (int it = tid; it < 512; it += 512) {
            int plane = it >> 8, r = (it >> 1) & 127, q = it & 1;
            const uint4 v = *(const uint4*)((plane ? Alo : Ahi) + (size_t)(rowbase + r)*H_ + k0 + q*8);
            *(uint4*)&sA[plane][r*PITCH + q*8] = v;
        }
#pragma unroll
        for (int it = tid; it < 512; it += 512) {
            int plane = it >> 8, r = (it >> 1) & 127, q = it & 1;
            const uint4 v = *(const uint4*)((plane ? Btlo : Bthi) + (size_t)(cb*128 + r)*H_ + k0 + q*8);
            *(uint4*)&sB[plane][r*PITCH + q*8] = v;
        }
        __syncthreads();
        uint32_t Ah[2][4], Al[2][4], Bh[8], Bl[8];
        ldsm4(Ah[0], aoff[0][0]); ldsm4(Ah[1], aoff[0][1]);
        ldsm4(Al[0], aoff[1][0]); ldsm4(Al[1], aoff[1][1]);
        ldsm4(Bh,   boff[0][0]); ldsm4(Bh+4, boff[0][1]);
        ldsm4(Bl,   boff[1][0]); ldsm4(Bl+4, boff[1][1]);
#pragma unroll
        for (int i = 0; i < 2; i++)
#pragma unroll
        for (int j = 0; j < 4; j++) {
            mma16816(acc[i][j], Ah[i], &Bh[j*2]);
            mma16816(acc[i][j], Ah[i], &Bl[j*2]);
            mma16816(acc[i][j], Al[i], &Bh[j*2]);
        }
        __syncthreads();
    }

    const int g8 = lane >> 2, t2 = (lane & 3)*2;
#pragma unroll
    for (int i = 0; i < 2; i++)
#pragma unroll
    for (int half = 0; half < 2; half++) {
        int grow = rowbase + wm*32 + i*16 + g8 + half*8;
#pragma unroll
        for (int j = 0; j < 4; j++) {
            int cc = cb*128 + wn*32 + j*8 + t2;
            float v0 = acc[i][j][half*2 + 0];
            float v1 = acc[i][j][half*2 + 1];
            if (bias) { v0 += bias[cc]; v1 += bias[cc+1]; }
            if (act == 1) { v0 = tanhf(v0); v1 = tanhf(v1); }
            float2 f2; f2.x = v0; f2.y = v1;
            *(float2*)&outf[(size_t)grow*E_ + cc] = f2;
            if (Phi) {
                __nv_bfloat162 hi2, lo2;
                hi2.x = __float2bfloat16(v0); hi2.y = __float2bfloat16(v1);
                lo2.x = __float2bfloat16(v0 - __bfloat162float(hi2.x));
                lo2.y = __float2bfloat16(v1 - __bfloat162float(hi2.y));
                *(__nv_bfloat162*)&Phi[(size_t)grow*E_ + cc] = hi2;
                *(__nv_bfloat162*)&Plo[(size_t)grow*E_ + cc] = lo2;
            }
        }
    }
}

// ------------------------- pre / alpha / reduce -----------------------------
__global__ void pre_kernel(const float* __restrict__ alpha_w,
                           const float* __restrict__ alpha_b) {
    int gw = (blockIdx.x*blockDim.x + threadIdx.x) >> 5;
    int lane = threadIdx.x & 31;
    if (gw >= NPACK_) return;
    int k = 0, off = 0;
    while (k < 62 && off + (63-k)*32 <= gw) { off += (63-k)*32; k++; }
    int l = gw - off;
    int t = l >> 5, b = l & 31;
    int p = k + t;
    const float* fa = g_fa + (size_t)gw*H_;
    float s = 0.f;
    for (int e = lane; e < H_; e += 32) s += fa[e]*alpha_w[e];
#pragma unroll
    for (int o=16;o;o>>=1) s += __shfl_xor_sync(0xffffffffu, s, o);
    if (lane == 0) g_pre[(p*T_ + t)*B_ + b] = s + alpha_b[0];
}

__global__ void alpha_kernel() {
    int gw = (blockIdx.x*blockDim.x + threadIdx.x) >> 5;
    int lane = threadIdx.x & 31;
    if (gw >= PB_) return;
    int p = gw >> 5, b = gw & 31;
    float v0 = (lane      <= p) ? g_pre[(p*T_+lane   )*B_+b] : -1e30f;
    float v1 = (lane + 32 <= p) ? g_pre[(p*T_+lane+32)*B_+b] : -1e30f;
    float m = fmaxf(v0, v1);
#pragma unroll
    for (int o=16;o;o>>=1) m = fmaxf(m, __shfl_xor_sync(0xffffffffu, m, o));
    float e0 = (lane      <= p) ? expf(v0-m) : 0.f;
    float e1 = (lane + 32 <= p) ? expf(v1-m) : 0.f;
    float s = e0 + e1;
#pragma unroll
    for (int o=16;o;o>>=1) s += __shfl_xor_sync(0xffffffffu, s, o);
    float inv = 1.f/s;
    g_alpha[(p*T_+lane   )*B_+b] = e0*inv;
    g_alpha[(p*T_+lane+32)*B_+b] = e1*inv;
}

__global__ void reduce_kernel(const float* __restrict__ x,
                              const float* __restrict__ out_w,
                              const float* __restrict__ out_b,
                              float* __restrict__ out) {
    int pb = blockIdx.x;
    int p = pb >> 5, b = pb & 31;
    int e = threadIdx.x;
    float cc = 0.f, gg = 0.f;
    for (int t = 0; t <= p; t++) {
        float a = g_alpha[(p*T_+t)*B_+b];
        int kk = p - t;
        int offk = 32*(63*kk - (kk*(kk-1))/2);
        size_t prow = (size_t)offk + t*32 + b;
        cc += a * g_beta [prow*E_ + e] * g_emb[((size_t)(t*B_+b))*E_ + e];
        gg += a * g_ebeta[prow*E_ + e] * x[((size_t)b*T_ + t)*E_ + e];
    }
    out[B_*P_ + ((size_t)(b*P_+p))*E_ + e] = gg / (float)(p+1);
    __shared__ float red[256];
    red[e] = cc * out_w[e];
    __syncthreads();
    for (int s2=128; s2; s2>>=1) { if (e < s2) red[e] += red[e+s2]; __syncthreads(); }
    if (e == 0) out[b*P_ + p] = red[0] + out_b[0];
}

// ------------------------- launch -------------------------------------------
extern "C" void kernel_launch(void* const* d_in, const int* in_sizes, int n_in,
                              void* d_out, int out_size) {
    (void)in_sizes; (void)n_in; (void)out_size;
    const float* x       = (const float*)d_in[0];
    const float* emb_w   = (const float*)d_in[1];
    const float* emb_b   = (const float*)d_in[2];
    const float* a_wih   = (const float*)d_in[3];
    const float* a_whh   = (const float*)d_in[4];
    const float* a_bih   = (const float*)d_in[5];
    const float* a_bhh   = (const float*)d_in[6];
    const float* b_wih   = (const float*)d_in[7];
    const float* b_whh   = (const float*)d_in[8];
    const float* b_bih   = (const float*)d_in[9];
    const float* b_bhh   = (const float*)d_in[10];
    const float* alpha_w = (const float*)d_in[11];
    const float* alpha_b = (const float*)d_in[12];
    const float* beta_w  = (const float*)d_in[13];
    const float* beta_b  = (const float*)d_in[14];
    const float* out_w   = (const float*)d_in[15];
    const float* out_b   = (const float*)d_in[16];
    float* out = (float*)d_out;

    cudaFuncSetAttribute(gru_persistent, cudaFuncAttributeMaxDynamicSharedMemorySize, SMEM_TOTAL_PERS);

    float *p_emb=0, *p_gxa=0, *p_gxb=0, *p_beta=0, *p_ebeta=0;
    __nv_bfloat16 *p_fbhi=0, *p_fblo=0, *p_bwhi=0, *p_bwlo=0;
    __nv_bfloat16 *p_mthi=0, *p_mtlo=0, *p_bhi=0, *p_blo=0;
    cudaGetSymbolAddress((void**)&p_emb,   g_emb);
    cudaGetSymbolAddress((void**)&p_gxa,   g_gxa);
    cudaGetSymbolAddress((void**)&p_gxb,   g_gxb);
    cudaGetSymbolAddress((void**)&p_beta,  g_beta);
    cudaGetSymbolAddress((void**)&p_ebeta, g_ebeta);
    cudaGetSymbolAddress((void**)&p_fbhi,  g_fbhi);
    cudaGetSymbolAddress((void**)&p_fblo,  g_fblo);
    cudaGetSymbolAddress((void**)&p_bwhi,  g_bwhi);
    cudaGetSymbolAddress((void**)&p_bwlo,  g_bwlo);
    cudaGetSymbolAddress((void**)&p_mthi,  g_mthi);
    cudaGetSymbolAddress((void**)&p_mtlo,  g_mtlo);
    cudaGetSymbolAddress((void**)&p_bhi,   g_betahi);
    cudaGetSymbolAddress((void**)&p_blo,   g_betalo);

    zero_planes_kernel<<<(2*2*PB_*H_/2 + 255)/256, 256>>>();
    prep_w_kernel<<<(2*768*256)/256, 256>>>(a_whh, b_whh);
    prep_bw_kernel<<<256, 256>>>(beta_w);
    prep_mt_kernel<<<256, 256>>>(emb_w, out_w);

    sgemm128<<<dim3((T_*B_)/128, E_/128), 256>>>(x, emb_w, emb_b, p_emb, E_, 0, 1);
    sgemm128<<<dim3((T_*B_)/128, (3*H_)/128), 256>>>(p_emb, a_wih, a_bih, p_gxa, 3*H_, 0, 0);
    sgemm128<<<dim3((T_*B_)/128, (3*H_)/128), 256>>>(p_emb, b_wih, b_bih, p_gxb, 3*H_, 0, 0);

    gru_persistent<<<NCTA_PERS, 512, SMEM_TOTAL_PERS>>>(a_bhh, b_bhh);

    pre_kernel<<<(NPACK_*32 + 255)/256, 256>>>(alpha_w, alpha_b);
    alpha_kernel<<<(PB_*32 + 255)/256, 256>>>();

    dense_mma<<<dim3(NPACK_/128, 2), 512>>>(p_fbhi, p_fblo, p_bwhi, p_bwlo,
                                            beta_b, 1, p_beta, p_bhi, p_blo);
    dense_mma<<<dim3(NPACK_/128, 2), 512>>>(p_bhi, p_blo, p_mthi, p_mtlo,
                                            (const float*)0, 0, p_ebeta,
                                            (__nv_bfloat16*)0, (__nv_bfloat16*)0);

    reduce_kernel<<<PB_, 256>>>(x, out_w, out_b, out);
}

// round 6
// speedup vs baseline: 1.8159x; 1.2423x over previous
#include <cuda_runtime.h>
#include <cuda_bf16.h>
#include <math.h>
#include <stdint.h>

#define B_ 32
#define T_ 64
#define E_ 256
#define H_ 256
#define P_ 63
#define PB_ 2016
#define NPACK_ 64512
#define PITCH 24   // bf16 elements per A smem row (16 data + 8 pad)

#define NCTA_PERS 128
#define SMEM_A_OFF   196608            // A buffers start (after 16 chunks * 12288B weights)
#define SMEM_TOTAL_PERS (196608 + 24576)

// ------------------------- scratch (device globals) -------------------------
__device__ float g_emb[T_*B_*E_];
__device__ float g_gxa[T_*B_*3*H_];
__device__ float g_gxb[T_*B_*3*H_];
__device__ __nv_bfloat16 g_hhi[2][2][PB_*H_];   // [gru][parity]
__device__ __nv_bfloat16 g_hlo[2][2][PB_*H_];
__device__ __nv_bfloat16 g_whi[2][3*H_*H_];     // recurrent weights, hi plane
__device__ __nv_bfloat16 g_wlo[2][3*H_*H_];
__device__ __nv_bfloat16 g_bwhi[E_*H_];
__device__ __nv_bfloat16 g_bwlo[E_*H_];
__device__ __nv_bfloat16 g_mthi[E_*E_];
__device__ __nv_bfloat16 g_mtlo[E_*E_];
__device__ float g_fa[(size_t)NPACK_*H_];
__device__ __nv_bfloat16 g_fbhi[(size_t)NPACK_*H_];
__device__ __nv_bfloat16 g_fblo[(size_t)NPACK_*H_];
__device__ float g_beta[(size_t)NPACK_*E_];
__device__ __nv_bfloat16 g_betahi[(size_t)NPACK_*E_];
__device__ __nv_bfloat16 g_betalo[(size_t)NPACK_*E_];
__device__ float g_ebeta[(size_t)NPACK_*E_];
__device__ float g_pre[P_*T_*B_];
__device__ float g_alpha[P_*T_*B_];
__device__ unsigned g_bar;

// ------------------------- helpers ------------------------------------------
__device__ __forceinline__ uint32_t smem_u32(const void* p) {
    uint32_t a;
    asm("{ .reg .u64 t; cvta.to.shared.u64 t, %1; cvt.u32.u64 %0, t; }" : "=r"(a) : "l"(p));
    return a;
}
__device__ __forceinline__ void ldsm4(uint32_t* r, uint32_t addr) {
    asm volatile("ldmatrix.sync.aligned.m8n8.x4.shared.b16 {%0,%1,%2,%3}, [%4];"
        : "=r"(r[0]), "=r"(r[1]), "=r"(r[2]), "=r"(r[3]) : "r"(addr));
}
__device__ __forceinline__ void mma16816(float* d, const uint32_t* a, const uint32_t* b) {
    asm volatile("mma.sync.aligned.m16n8k16.row.col.f32.bf16.bf16.f32 "
        "{%0,%1,%2,%3}, {%4,%5,%6,%7}, {%8,%9}, {%0,%1,%2,%3};"
        : "+f"(d[0]), "+f"(d[1]), "+f"(d[2]), "+f"(d[3])
        : "r"(a[0]), "r"(a[1]), "r"(a[2]), "r"(a[3]), "r"(b[0]), "r"(b[1]));
}
#define CP_ASYNC16(dst, src) \
    asm volatile("cp.async.cg.shared.global [%0], [%1], 16;" :: "r"(dst), "l"(src))
#define CP_COMMIT() asm volatile("cp.async.commit_group;")
#define CP_WAIT1()  asm volatile("cp.async.wait_group 1;")
#define CP_WAIT0()  asm volatile("cp.async.wait_group 0;")

// ------------------------- prep kernels -------------------------------------
__global__ void zero_planes_kernel() {
    int i = blockIdx.x*256 + threadIdx.x;
    uint32_t* a = (uint32_t*)g_hhi;
    uint32_t* b = (uint32_t*)g_hlo;
    if (i < 2*2*PB_*H_/2) { a[i] = 0u; b[i] = 0u; }
    if (i == 0) g_bar = 0u;
}
__global__ void prep_w_kernel(const float* __restrict__ wa, const float* __restrict__ wb) {
    int idx = blockIdx.x*256 + threadIdx.x;
    int k = idx & 255;
    int r = (idx >> 8) % 768;
    int gru = idx / (768*256);
    float v = (gru ? wb : wa)[r*256 + k];
    __nv_bfloat16 hi = __float2bfloat16(v);
    g_whi[gru][r*256 + k] = hi;
    g_wlo[gru][r*256 + k] = __float2bfloat16(v - __bfloat162float(hi));
}
__global__ void prep_bw_kernel(const float* __restrict__ bw) {
    int idx = blockIdx.x*256 + threadIdx.x;
    float v = bw[idx];
    __nv_bfloat16 hi = __float2bfloat16(v);
    g_bwhi[idx] = hi;
    g_bwlo[idx] = __float2bfloat16(v - __bfloat162float(hi));
}
__global__ void prep_mt_kernel(const float* __restrict__ emb_w, const float* __restrict__ out_w) {
    int idx = blockIdx.x*256 + threadIdx.x;
    int i = idx >> 8, e = idx & 255;
    float v = out_w[e] * emb_w[e*256 + i];
    __nv_bfloat16 hi = __float2bfloat16(v);
    g_mthi[idx] = hi;
    g_mtlo[idx] = __float2bfloat16(v - __bfloat162float(hi));
}

// ------------------------- fp32 SGEMM (emb / gx) ----------------------------
__device__ __forceinline__ const float* arow_ptr(const float* A, int m, int xmode) {
    if (xmode) { int t = m >> 5, b = m & 31; return A + ((size_t)b*T_ + t)*E_; }
    return A + (size_t)m*E_;
}
__global__ void __launch_bounds__(256, 2)
sgemm128(const float* __restrict__ A, const float* __restrict__ Bt,
         const float* __restrict__ bias, float* __restrict__ C,
         int N, int act, int xmode) {
    __shared__ float As[2][8][128];
    __shared__ float Bs[2][8][128];
    const int tid = threadIdx.x;
    const int m0 = blockIdx.x * 128, n0 = blockIdx.y * 128;
    const int tx = tid & 15, ty = tid >> 4;
    const int lr = tid >> 1;
    const int ks = (tid & 1) * 4;
    const float* pA = arow_ptr(A, m0 + lr, xmode) + ks;
    const float* pB = Bt + (size_t)(n0 + lr) * 256 + ks;
    float acc[2][2][4][4] = {};
    float4 va = *(const float4*)pA;
    float4 vb = *(const float4*)pB;
    {
        const float* f = (const float*)&va;
#pragma unroll
        for (int j = 0; j < 4; j++) As[0][ks+j][lr] = f[j];
        f = (const float*)&vb;
#pragma unroll
        for (int j = 0; j < 4; j++) Bs[0][ks+j][lr] = f[j];
    }
    __syncthreads();
    int buf = 0;
#pragma unroll 1
    for (int c = 0; c < 32; c++) {
        if (c < 31) {
            int off = (c+1)*8;
            va = *(const float4*)(pA + off);
            vb = *(const float4*)(pB + off);
        }
#pragma unroll
        for (int kk = 0; kk < 8; kk++) {
            float4 a0 = *(const float4*)&As[buf][kk][ty*4];
            float4 a1 = *(const float4*)&As[buf][kk][ty*4 + 64];
            float4 b0 = *(const float4*)&Bs[buf][kk][tx*4];
            float4 b1 = *(const float4*)&Bs[buf][kk][tx*4 + 64];
            float aa[2][4] = {{a0.x,a0.y,a0.z,a0.w},{a1.x,a1.y,a1.z,a1.w}};
            float bb[2][4] = {{b0.x,b0.y,b0.z,b0.w},{b1.x,b1.y,b1.z,b1.w}};
#pragma unroll
            for (int rh = 0; rh < 2; rh++)
#pragma unroll
            for (int i = 0; i < 4; i++)
#pragma unroll
            for (int ch = 0; ch < 2; ch++)
#pragma unroll
            for (int j = 0; j < 4; j++)
                acc[rh][ch][i][j] = fmaf(aa[rh][i], bb[ch][j], acc[rh][ch][i][j]);
        }
        if (c < 31) {
            int nb = buf ^ 1;
            const float* f = (const float*)&va;
#pragma unroll
            for (int j = 0; j < 4; j++) As[nb][ks+j][lr] = f[j];
            f = (const float*)&vb;
#pragma unroll
            for (int j = 0; j < 4; j++) Bs[nb][ks+j][lr] = f[j];
            __syncthreads();
            buf = nb;
        }
    }
#pragma unroll
    for (int rh = 0; rh < 2; rh++)
#pragma unroll
    for (int i = 0; i < 4; i++) {
        int m = m0 + rh*64 + ty*4 + i;
#pragma unroll
        for (int ch = 0; ch < 2; ch++) {
            int n = n0 + ch*64 + tx*4;
            float4 v;
            v.x = acc[rh][ch][i][0]; v.y = acc[rh][ch][i][1];
            v.z = acc[rh][ch][i][2]; v.w = acc[rh][ch][i][3];
            if (bias) {
                float4 bz = *(const float4*)&bias[n];
                v.x += bz.x; v.y += bz.y; v.z += bz.z; v.w += bz.w;
            }
            if (act == 1) { v.x = tanhf(v.x); v.y = tanhf(v.y); v.z = tanhf(v.z); v.w = tanhf(v.w); }
            *(float4*)&C[(size_t)m*N + n] = v;
        }
    }
}

// ------------------------- persistent GRU recurrence (balanced) -------------
// Grid: 128 CTAs x 512 thr. CTA = (gru, cb, q). Per step, the (63-k)*2
// 16-row chunks of active rows are split evenly over the 16 q-CTAs.
__global__ void __launch_bounds__(512, 1)
gru_persistent(const float* __restrict__ bhh_a, const float* __restrict__ bhh_b) {
    extern __shared__ __align__(16) unsigned char smem[];
    const int tid = threadIdx.x, lane = tid & 31, wid = tid >> 5;
    const int wm = wid & 3, wn = wid >> 2;
    const int gid = blockIdx.x;
    const int gru = gid & 1, cb = (gid >> 1) & 3, q = gid >> 3;
    const uint32_t sbase = smem_u32(smem);

    // ---- one-time: load weight slice (3 gates x 64 cols, K=256, 2 planes) ----
    {
        const __nv_bfloat16* Whi = g_whi[gru];
        const __nv_bfloat16* Wlo = g_wlo[gru];
        for (int it = tid; it < 12288; it += 512) {
            int qq = it & 1;
            int r = (it >> 1) % 192;
            int t3 = (it >> 1) / 192;
            int p = t3 & 1;
            int c = t3 >> 1;
            int R = (r >> 6)*256 + cb*64 + (r & 63);
            const __nv_bfloat16* src = (p ? Wlo : Whi) + (size_t)R*256 + c*16 + qq*8;
            *(uint4*)(smem + c*12288 + p*6144 + r*32 + qq*16) = *(const uint4*)src;
        }
    }
    __syncthreads();

    // ---- per-lane ldmatrix offsets ----
    const int a_r = lane & 15, a_c = ((lane >> 4) & 1) * 8;
    const int b_r = (lane & 7) + ((lane >> 4) & 1) * 8, b_c16 = (lane & 8) * 2;
    uint32_t abase[2][2][2];   // [buf][plane][i]
#pragma unroll
    for (int bf = 0; bf < 2; bf++)
#pragma unroll
    for (int p = 0; p < 2; p++)
#pragma unroll
    for (int i = 0; i < 2; i++)
        abase[bf][p][i] = sbase + SMEM_A_OFF + bf*12288u + p*6144u
                        + (uint32_t)((wm*32 + i*16 + a_r)*48 + a_c*2);
    uint32_t wboff[2][3];      // [plane][gate]
#pragma unroll
    for (int p = 0; p < 2; p++)
#pragma unroll
    for (int g = 0; g < 3; g++)
        wboff[p][g] = (uint32_t)(p*6144 + (g*64 + wn*16 + b_r)*32 + b_c16);

    const float* bhh = gru ? bhh_b : bhh_a;
    const float* gx  = gru ? g_gxb : g_gxa;
    const int st_q = tid & 1, st_r = (tid >> 1) & 127, st_p = tid >> 8;
    const uint32_t st_dst0 = sbase + SMEM_A_OFF + st_p*6144u + (uint32_t)(st_r*48 + st_q*16);

    const int g8 = lane >> 2, t2 = (lane & 3)*2;

#pragma unroll 1
    for (int step = 0; step < 63; step++) {
        const int par = step & 1;
        const int nch = (63 - step)*2;            // 16-row chunks available
        const int per = (nch + 15) >> 4;          // chunks per CTA
        const int myc = q*per;
        int R = 0;
        if (myc < nch) { int c = nch - myc; R = (c < per ? c : per)*16; }
        if (R > 0) {
            const __nv_bfloat16* Hhi = g_hhi[gru][par];
            const __nv_bfloat16* Hlo = g_hlo[gru][par];
            const int rowbase = step*32 + myc*16;
            const int ng = R >> 4;                // active 16-row groups (1..8)
            const __nv_bfloat16* st_src = (st_p ? Hlo : Hhi)
                + (size_t)(rowbase + (st_r < R ? st_r : 0))*H_ + st_q*8;
            const bool st_on = (st_r < R);

            float acc[3][2][2][4] = {};
            if (st_on) CP_ASYNC16(st_dst0, st_src);
            CP_COMMIT();
#pragma unroll 1
            for (int c = 0; c < 16; c++) {
                if (c < 15) {
                    if (st_on) CP_ASYNC16(st_dst0 + (uint32_t)(((c+1)&1)*12288), st_src + (c+1)*16);
                    CP_COMMIT();
                    CP_WAIT1();
                } else {
                    CP_WAIT0();
                }
                __syncthreads();
                if (2*wm < ng) {
                    const int bf = c & 1;
                    const bool two = (2*wm + 1 < ng);
                    uint32_t Ah[2][4], Al[2][4];
                    ldsm4(Ah[0], abase[bf][0][0]);
                    ldsm4(Al[0], abase[bf][1][0]);
                    if (two) { ldsm4(Ah[1], abase[bf][0][1]); ldsm4(Al[1], abase[bf][1][1]); }
                    const uint32_t wbc = sbase + (uint32_t)(c*12288);
#pragma unroll
                    for (int g = 0; g < 3; g++) {
                        uint32_t Bh[4], Bl[4];
                        ldsm4(Bh, wbc + wboff[0][g]);
                        ldsm4(Bl, wbc + wboff[1][g]);
#pragma unroll
                        for (int j = 0; j < 2; j++) {
                            mma16816(acc[g][0][j], Ah[0], &Bh[j*2]);
                            mma16816(acc[g][0][j], Ah[0], &Bl[j*2]);
                            mma16816(acc[g][0][j], Al[0], &Bh[j*2]);
                        }
                        if (two) {
#pragma unroll
                            for (int j = 0; j < 2; j++) {
                                mma16816(acc[g][1][j], Ah[1], &Bh[j*2]);
                                mma16816(acc[g][1][j], Ah[1], &Bl[j*2]);
                                mma16816(acc[g][1][j], Al[1], &Bh[j*2]);
                            }
                        }
                    }
                }
                __syncthreads();
            }
            // ---- epilogue ----
            __nv_bfloat16* Hhi_n = g_hhi[gru][par^1];
            __nv_bfloat16* Hlo_n = g_hlo[gru][par^1];
            const size_t offk = (size_t)32*(63*step - (step*(step-1))/2);
#pragma unroll
            for (int i = 0; i < 2; i++) {
                if (2*wm + i >= ng) continue;
#pragma unroll
                for (int half = 0; half < 2; half++) {
                    int grow = rowbase + wm*32 + i*16 + g8 + half*8;
                    int gxrow = grow - step*32;
                    const float* gxr = gx + (size_t)gxrow*(3*H_);
                    size_t prow = offk + gxrow;
#pragma unroll
                    for (int j = 0; j < 2; j++) {
                        int cc = cb*64 + wn*16 + j*8 + t2;
                        float2 gx_r = *(const float2*)&gxr[cc];
                        float2 gx_z = *(const float2*)&gxr[H_ + cc];
                        float2 gx_n = *(const float2*)&gxr[2*H_ + cc];
                        float2 bh_r = *(const float2*)&bhh[cc];
                        float2 bh_z = *(const float2*)&bhh[H_ + cc];
                        float2 bh_n = *(const float2*)&bhh[2*H_ + cc];
                        __nv_bfloat162 ho_hi = *(const __nv_bfloat162*)&Hhi[(size_t)grow*H_ + cc];
                        __nv_bfloat162 ho_lo = *(const __nv_bfloat162*)&Hlo[(size_t)grow*H_ + cc];
                        float hn2[2];
#pragma unroll
                        for (int u = 0; u < 2; u++) {
                            int ai = half*2 + u;
                            float rp = acc[0][i][j][ai] + (u ? bh_r.y : bh_r.x) + (u ? gx_r.y : gx_r.x);
                            float zp = acc[1][i][j][ai] + (u ? bh_z.y : bh_z.x) + (u ? gx_z.y : gx_z.x);
                            float np = acc[2][i][j][ai] + (u ? bh_n.y : bh_n.x);
                            float r = 1.f/(1.f + expf(-rp));
                            float z = 1.f/(1.f + expf(-zp));
                            float n = tanhf((u ? gx_n.y : gx_n.x) + r*np);
                            float hold = __bfloat162float(u ? ho_hi.y : ho_hi.x)
                                       + __bfloat162float(u ? ho_lo.y : ho_lo.x);
                            hn2[u] = (1.f - z)*n + z*hold;
                        }
                        __nv_bfloat162 hi2, lo2;
                        hi2.x = __float2bfloat16(hn2[0]); hi2.y = __float2bfloat16(hn2[1]);
                        lo2.x = __float2bfloat16(hn2[0] - __bfloat162float(hi2.x));
                        lo2.y = __float2bfloat16(hn2[1] - __bfloat162float(hi2.y));
                        *(__nv_bfloat162*)&Hhi_n[(size_t)grow*H_ + cc] = hi2;
                        *(__nv_bfloat162*)&Hlo_n[(size_t)grow*H_ + cc] = lo2;
                        if (gru == 0) {
                            float2 f2; f2.x = 0.5f*hn2[0]; f2.y = 0.5f*hn2[1];
                            *(float2*)&g_fa[prow*H_ + cc] = f2;
                        } else {
                            float f0 = 0.5f*hn2[0], f1 = 0.5f*hn2[1];
                            __nv_bfloat162 fh, fl;
                            fh.x = __float2bfloat16(f0); fh.y = __float2bfloat16(f1);
                            fl.x = __float2bfloat16(f0 - __bfloat162float(fh.x));
                            fl.y = __float2bfloat16(f1 - __bfloat162float(fh.y));
                            *(__nv_bfloat162*)&g_fbhi[prow*H_ + cc] = fh;
                            *(__nv_bfloat162*)&g_fblo[prow*H_ + cc] = fl;
                        }
                    }
                }
            }
        }
        // ---- grid-wide barrier ----
        __syncthreads();
        if (tid == 0) {
            __threadfence();
            atomicAdd(&g_bar, 1u);
            const unsigned target = (unsigned)NCTA_PERS*(step+1);
            unsigned v;
            do {
                asm volatile("ld.acquire.gpu.u32 %0, [%1];" : "=r"(v) : "l"(&g_bar));
            } while (v < target);
        }
        __syncthreads();
    }
}

// ------------------------- mma dense GEMM (M x 256, K=256) ------------------
__global__ void __launch_bounds__(512, 1)
dense_mma(const __nv_bfloat16* __restrict__ Ahi, const __nv_bfloat16* __restrict__ Alo,
          const __nv_bfloat16* __restrict__ Bthi, const __nv_bfloat16* __restrict__ Btlo,
          const float* __restrict__ bias, int act, float* __restrict__ outf,
          __nv_bfloat16* __restrict__ Phi, __nv_bfloat16* __restrict__ Plo) {
    __shared__ __align__(16) __nv_bfloat16 sA[2][128*PITCH];
    __shared__ __align__(16) __nv_bfloat16 sB[2][128*PITCH];
    const int tid = threadIdx.x, lane = tid & 31, wid = tid >> 5;
    const int wm = wid & 3, wn = wid >> 2;
    const int cb = blockIdx.y;
    const int rowbase = blockIdx.x * 128;

    float acc[2][4][4] = {};

    const int a_r = lane & 15, a_c = ((lane >> 4) & 1) * 8;
    const int b_r = (lane & 7) + ((lane >> 4) & 1) * 8, b_c = lane & 8;
    uint32_t aoff[2][2], boff[2][2];
#pragma unroll
    for (int p = 0; p < 2; p++) {
        uint32_t ab = smem_u32(&sA[p][0]);
        uint32_t bb = smem_u32(&sB[p][0]);
#pragma unroll
        for (int i = 0; i < 2; i++)
            aoff[p][i] = ab + ((wm*32 + i*16 + a_r)*PITCH + a_c)*2;
#pragma unroll
        for (int h2 = 0; h2 < 2; h2++)
            boff[p][h2] = bb + ((wn*32 + h2*16 + b_r)*PITCH + b_c)*2;
    }

#pragma unroll 1
    for (int c = 0; c < 16; c++) {
        int k0 = c*16;
#pragma unroll
        for (int it = tid; it < 512; it += 512) {
            int plane = it >> 8, r = (it >> 1) & 127, q = it & 1;
            const uint4 v = *(const uint4*)((plane ? Alo : Ahi) + (size_t)(rowbase + r)*H_ + k0 + q*8);
            *(uint4*)&sA[plane][r*PITCH + q*8] = v;
        }
#pragma unroll
        for (int it = tid; it < 512; it += 512) {
            int plane = it >> 8, r = (it >> 1) & 127, q = it & 1;
            const uint4 v = *(const uint4*)((plane ? Btlo : Bthi) + (size_t)(cb*128 + r)*H_ + k0 + q*8);
            *(uint4*)&sB[plane][r*PITCH + q*8] = v;
        }
        __syncthreads();
        uint32_t Ah[2][4], Al[2][4], Bh[8], Bl[8];
        ldsm4(Ah[0], aoff[0][0]); ldsm4(Ah[1], aoff[0][1]);
        ldsm4(Al[0], aoff[1][0]); ldsm4(Al[1], aoff[1][1]);
        ldsm4(Bh,   boff[0][0]); ldsm4(Bh+4, boff[0][1]);
        ldsm4(Bl,   boff[1][0]); ldsm4(Bl+4, boff[1][1]);
#pragma unroll
        for (int i = 0; i < 2; i++)
#pragma unroll
        for (int j = 0; j < 4; j++) {
            mma16816(acc[i][j], Ah[i], &Bh[j*2]);
            mma16816(acc[i][j], Ah[i], &Bl[j*2]);
            mma16816(acc[i][j], Al[i], &Bh[j*2]);
        }
        __syncthreads();
    }

    const int g8 = lane >> 2, t2 = (lane & 3)*2;
#pragma unroll
    for (int i = 0; i < 2; i++)
#pragma unroll
    for (int half = 0; half < 2; half++) {
        int grow = rowbase + wm*32 + i*16 + g8 + half*8;
#pragma unroll
        for (int j = 0; j < 4; j++) {
            int cc = cb*128 + wn*32 + j*8 + t2;
            float v0 = acc[i][j][half*2 + 0];
            float v1 = acc[i][j][half*2 + 1];
            if (bias) { v0 += bias[cc]; v1 += bias[cc+1]; }
            if (act == 1) { v0 = tanhf(v0); v1 = tanhf(v1); }
            float2 f2; f2.x = v0; f2.y = v1;
            *(float2*)&outf[(size_t)grow*E_ + cc] = f2;
            if (Phi) {
                __nv_bfloat162 hi2, lo2;
                hi2.x = __float2bfloat16(v0); hi2.y = __float2bfloat16(v1);
                lo2.x = __float2bfloat16(v0 - __bfloat162float(hi2.x));
                lo2.y = __float2bfloat16(v1 - __bfloat162float(hi2.y));
                *(__nv_bfloat162*)&Phi[(size_t)grow*E_ + cc] = hi2;
                *(__nv_bfloat162*)&Plo[(size_t)grow*E_ + cc] = lo2;
            }
        }
    }
}

// ------------------------- pre / alpha / reduce -----------------------------
__global__ void pre_kernel(const float* __restrict__ alpha_w,
                           const float* __restrict__ alpha_b) {
    int gw = (blockIdx.x*blockDim.x + threadIdx.x) >> 5;
    int lane = threadIdx.x & 31;
    if (gw >= NPACK_) return;
    int k = 0, off = 0;
    while (k < 62 && off + (63-k)*32 <= gw) { off += (63-k)*32; k++; }
    int l = gw - off;
    int t = l >> 5, b = l & 31;
    int p = k + t;
    const float* fa = g_fa + (size_t)gw*H_;
    float s = 0.f;
    for (int e = lane; e < H_; e += 32) s += fa[e]*alpha_w[e];
#pragma unroll
    for (int o=16;o;o>>=1) s += __shfl_xor_sync(0xffffffffu, s, o);
    if (lane == 0) g_pre[(p*T_ + t)*B_ + b] = s + alpha_b[0];
}

__global__ void alpha_kernel() {
    int gw = (blockIdx.x*blockDim.x + threadIdx.x) >> 5;
    int lane = threadIdx.x & 31;
    if (gw >= PB_) return;
    int p = gw >> 5, b = gw & 31;
    float v0 = (lane      <= p) ? g_pre[(p*T_+lane   )*B_+b] : -1e30f;
    float v1 = (lane + 32 <= p) ? g_pre[(p*T_+lane+32)*B_+b] : -1e30f;
    float m = fmaxf(v0, v1);
#pragma unroll
    for (int o=16;o;o>>=1) m = fmaxf(m, __shfl_xor_sync(0xffffffffu, m, o));
    float e0 = (lane      <= p) ? expf(v0-m) : 0.f;
    float e1 = (lane + 32 <= p) ? expf(v1-m) : 0.f;
    float s = e0 + e1;
#pragma unroll
    for (int o=16;o;o>>=1) s += __shfl_xor_sync(0xffffffffu, s, o);
    float inv = 1.f/s;
    g_alpha[(p*T_+lane   )*B_+b] = e0*inv;
    g_alpha[(p*T_+lane+32)*B_+b] = e1*inv;
}

__global__ void reduce_kernel(const float* __restrict__ x,
                              const float* __restrict__ out_w,
                              const float* __restrict__ out_b,
                              float* __restrict__ out) {
    int pb = blockIdx.x;
    int p = pb >> 5, b = pb & 31;
    int e = threadIdx.x;
    float cc = 0.f, gg = 0.f;
    for (int t = 0; t <= p; t++) {
        float a = g_alpha[(p*T_+t)*B_+b];
        int kk = p - t;
        int offk = 32*(63*kk - (kk*(kk-1))/2);
        size_t prow = (size_t)offk + t*32 + b;
        cc += a * g_beta [prow*E_ + e] * g_emb[((size_t)(t*B_+b))*E_ + e];
        gg += a * g_ebeta[prow*E_ + e] * x[((size_t)b*T_ + t)*E_ + e];
    }
    out[B_*P_ + ((size_t)(b*P_+p))*E_ + e] = gg / (float)(p+1);
    __shared__ float red[256];
    red[e] = cc * out_w[e];
    __syncthreads();
    for (int s2=128; s2; s2>>=1) { if (e < s2) red[e] += red[e+s2]; __syncthreads(); }
    if (e == 0) out[b*P_ + p] = red[0] + out_b[0];
}

// ------------------------- launch -------------------------------------------
extern "C" void kernel_launch(void* const* d_in, const int* in_sizes, int n_in,
                              void* d_out, int out_size) {
    (void)in_sizes; (void)n_in; (void)out_size;
    const float* x       = (const float*)d_in[0];
    const float* emb_w   = (const float*)d_in[1];
    const float* emb_b   = (const float*)d_in[2];
    const float* a_wih   = (const float*)d_in[3];
    const float* a_whh   = (const float*)d_in[4];
    const float* a_bih   = (const float*)d_in[5];
    const float* a_bhh   = (const float*)d_in[6];
    const float* b_wih   = (const float*)d_in[7];
    const float* b_whh   = (const float*)d_in[8];
    const float* b_bih   = (const float*)d_in[9];
    const float* b_bhh   = (const float*)d_in[10];
    const float* alpha_w = (const float*)d_in[11];
    const float* alpha_b = (const float*)d_in[12];
    const float* beta_w  = (const float*)d_in[13];
    const float* beta_b  = (const float*)d_in[14];
    const float* out_w   = (const float*)d_in[15];
    const float* out_b   = (const float*)d_in[16];
    float* out = (float*)d_out;

    cudaFuncSetAttribute(gru_persistent, cudaFuncAttributeMaxDynamicSharedMemorySize, SMEM_TOTAL_PERS);

    float *p_emb=0, *p_gxa=0, *p_gxb=0, *p_beta=0, *p_ebeta=0;
    __nv_bfloat16 *p_fbhi=0, *p_fblo=0, *p_bwhi=0, *p_bwlo=0;
    __nv_bfloat16 *p_mthi=0, *p_mtlo=0, *p_bhi=0, *p_blo=0;
    cudaGetSymbolAddress((void**)&p_emb,   g_emb);
    cudaGetSymbolAddress((void**)&p_gxa,   g_gxa);
    cudaGetSymbolAddress((void**)&p_gxb,   g_gxb);
    cudaGetSymbolAddress((void**)&p_beta,  g_beta);
    cudaGetSymbolAddress((void**)&p_ebeta, g_ebeta);
    cudaGetSymbolAddress((void**)&p_fbhi,  g_fbhi);
    cudaGetSymbolAddress((void**)&p_fblo,  g_fblo);
    cudaGetSymbolAddress((void**)&p_bwhi,  g_bwhi);
    cudaGetSymbolAddress((void**)&p_bwlo,  g_bwlo);
    cudaGetSymbolAddress((void**)&p_mthi,  g_mthi);
    cudaGetSymbolAddress((void**)&p_mtlo,  g_mtlo);
    cudaGetSymbolAddress((void**)&p_bhi,   g_betahi);
    cudaGetSymbolAddress((void**)&p_blo,   g_betalo);

    zero_planes_kernel<<<(2*2*PB_*H_/2 + 255)/256, 256>>>();
    prep_w_kernel<<<(2*768*256)/256, 256>>>(a_whh, b_whh);
    prep_bw_kernel<<<256, 256>>>(beta_w);
    prep_mt_kernel<<<256, 256>>>(emb_w, out_w);

    sgemm128<<<dim3((T_*B_)/128, E_/128), 256>>>(x, emb_w, emb_b, p_emb, E_, 0, 1);
    sgemm128<<<dim3((T_*B_)/128, (3*H_)/128), 256>>>(p_emb, a_wih, a_bih, p_gxa, 3*H_, 0, 0);
    sgemm128<<<dim3((T_*B_)/128, (3*H_)/128), 256>>>(p_emb, b_wih, b_bih, p_gxb, 3*H_, 0, 0);

    gru_persistent<<<NCTA_PERS, 512, SMEM_TOTAL_PERS>>>(a_bhh, b_bhh);

    pre_kernel<<<(NPACK_*32 + 255)/256, 256>>>(alpha_w, alpha_b);
    alpha_kernel<<<(PB_*32 + 255)/256, 256>>>();

    dense_mma<<<dim3(NPACK_/128, 2), 512>>>(p_fbhi, p_fblo, p_bwhi, p_bwlo,
                                            beta_b, 1, p_beta, p_bhi, p_blo);
    dense_mma<<<dim3(NPACK_/128, 2), 512>>>(p_bhi, p_blo, p_mthi, p_mtlo,
                                            (const float*)0, 0, p_ebeta,
                                            (__nv_bfloat16*)0, (__nv_bfloat16*)0);

    reduce_kernel<<<PB_, 256>>>(x, out_w, out_b, out);
}